// round 10
// baseline (speedup 1.0000x reference)
#include <cuda_runtime.h>
#include <cuda_bf16.h>
#include <cstdint>

// ---------------------------------------------------------------------------
// DeBERTa-style disentangled attention.
// B=8 S=384 IN=512 E=512 H=8 D=64, rel offsets t in [0,767), table row t+128.
// R10: GEMM core software-pipelined: double-buffered bf16 hi/lo smem tiles,
//      LDG of next tile overlapped with MMA of current (1 sync/iter).
//      bf16 m16n8k16 3-term (Ah*Bh+Ah*Bl+Al*Bh). Attention unchanged.
// ---------------------------------------------------------------------------

#define KB 8
#define KS 384
#define KIN 512
#define KE 512
#define KH 8
#define KD 64
#define KT 767            // 2*S-1 (logical)
#define KTP 768           // padded row stride for c2p/p2c scratch
#define KRELOFF 128       // table row = t + 128
#define KSCALE 0.07216878364870323f   // 1/sqrt(64*3)

#define BKP 40            // bf16 smem row stride (elems) = 80B -> frag LDS conflict-free
#define TSZ (128*BKP)     // one tile buffer (elems)

__device__ float g_q[KB*KH*KS*KD];
__device__ float g_k[KB*KH*KS*KD];
__device__ float g_v[KB*KH*KS*KD];
__device__ float g_pk[KH*KT*KD];
__device__ float g_pq[KH*KT*KD];
__device__ float g_c2p[(size_t)KB*KH*KS*KTP];
__device__ float g_p2c[(size_t)KB*KH*KS*KTP];
__device__ float g_ctx[KB*KS*KE];

// ---------------------------------------------------------------------------
// bf16 helpers
// ---------------------------------------------------------------------------
__device__ __forceinline__ void bsplit(float x, __nv_bfloat16& h, __nv_bfloat16& l)
{
    h = __float2bfloat16_rn(x);
    l = __float2bfloat16_rn(x - __bfloat162float(h));
}

__device__ __forceinline__ uint32_t pack2(__nv_bfloat16 a, __nv_bfloat16 b)
{
    __nv_bfloat162 t(a, b);
    return *reinterpret_cast<uint32_t*>(&t);
}

__device__ __forceinline__ void mma_bf16(float* d,
    uint32_t a0, uint32_t a1, uint32_t a2, uint32_t a3,
    uint32_t b0, uint32_t b1)
{
    asm("mma.sync.aligned.m16n8k16.row.col.f32.bf16.bf16.f32 "
        "{%0,%1,%2,%3}, {%4,%5,%6,%7}, {%8,%9}, {%0,%1,%2,%3};"
        : "+f"(d[0]), "+f"(d[1]), "+f"(d[2]), "+f"(d[3])
        : "r"(a0), "r"(a1), "r"(a2), "r"(a3), "r"(b0), "r"(b1));
}

// ---------------------------------------------------------------------------
// Tile stage helpers: 128 rows x 32 k, 256 threads, each thread 4 float4.
// ---------------------------------------------------------------------------
__device__ __forceinline__ void ldg_tile(
    const float* __restrict__ P, int ldp, int r0, int Rlim, int k0, float4 v[4])
{
    const int tid = threadIdx.x;
    const int lrow = tid >> 3;         // 0..31
    const int lk = (tid & 7) * 4;      // 0..28
    #pragma unroll
    for (int h4 = 0; h4 < 4; h4++) {
        const int r = r0 + lrow + h4*32;
        v[h4] = make_float4(0.f, 0.f, 0.f, 0.f);
        if (r < Rlim)
            v[h4] = *(const float4*)(P + (size_t)r * ldp + k0 + lk);
    }
}

__device__ __forceinline__ void sts_tile(
    const float4 v[4], __nv_bfloat16* H, __nv_bfloat16* L)
{
    const int tid = threadIdx.x;
    const int lrow = tid >> 3;
    const int lk = (tid & 7) * 4;
    #pragma unroll
    for (int h4 = 0; h4 < 4; h4++) {
        const int row = lrow + h4*32;
        __nv_bfloat16 hx,hy,hz,hw, lx,ly,lz,lw;
        bsplit(v[h4].x,hx,lx); bsplit(v[h4].y,hy,ly);
        bsplit(v[h4].z,hz,lz); bsplit(v[h4].w,hw,lw);
        *(uint2*)&H[row*BKP + lk] = make_uint2(pack2(hx,hy), pack2(hz,hw));
        *(uint2*)&L[row*BKP + lk] = make_uint2(pack2(lx,ly), pack2(lz,lw));
    }
}

// ---------------------------------------------------------------------------
// 128x128 tile GEMM core, 256 threads (8 warps), BK=32, bf16 3-term mma,
// double-buffered smem + reg prefetch: per iter STS -> sync -> LDG(next)
// -> MMA.  C = A @ Bm^T, A:[Mlim x lda], Bm:[Nlim x ldb] row-major.
// Warp (warp>>2)*64 x (warp&3)*32 sub-tile: 4 m-frags x 4 n-frags.
// K must be a multiple of 32.
// ---------------------------------------------------------------------------
__device__ __forceinline__ void mma128_core(
    const float* __restrict__ A, int lda, int a0r, int Mlim,
    const float* __restrict__ Bm, int ldb, int b0r, int Nlim,
    int K, float acc[4][4][4],
    __nv_bfloat16* Ah, __nv_bfloat16* Al,
    __nv_bfloat16* Bh, __nv_bfloat16* Bl)
{
    const int tid = threadIdx.x;
    const int lane = tid & 31, warp = tid >> 5;
    const int wm = (warp >> 2) * 64;
    const int wn = (warp & 3) * 32;
    const int g = lane >> 2, tig = lane & 3;

    const int nIt = K >> 5;
    float4 va[4], vb[4];
    ldg_tile(A, lda, a0r, Mlim, 0, va);
    ldg_tile(Bm, ldb, b0r, Nlim, 0, vb);

    int buf = 0;
    for (int it = 0; it < nIt; it++) {
        __nv_bfloat16* ah = Ah + buf*TSZ; __nv_bfloat16* al = Al + buf*TSZ;
        __nv_bfloat16* bhp = Bh + buf*TSZ; __nv_bfloat16* blp = Bl + buf*TSZ;
        sts_tile(va, ah, al);
        sts_tile(vb, bhp, blp);
        __syncthreads();
        if (it + 1 < nIt) {
            ldg_tile(A, lda, a0r, Mlim, (it+1)*32, va);
            ldg_tile(Bm, ldb, b0r, Nlim, (it+1)*32, vb);
        }
        #pragma unroll
        for (int kk = 0; kk < 32; kk += 16) {
            uint32_t bh0[4], bh1[4], bl0[4], bl1[4];
            #pragma unroll
            for (int nf = 0; nf < 4; nf++) {
                const int nb = (wn + nf*8 + g)*BKP + kk + 2*tig;
                bh0[nf] = *(const uint32_t*)&bhp[nb];
                bh1[nf] = *(const uint32_t*)&bhp[nb + 8];
                bl0[nf] = *(const uint32_t*)&blp[nb];
                bl1[nf] = *(const uint32_t*)&blp[nb + 8];
            }
            #pragma unroll
            for (int mf = 0; mf < 4; mf++) {
                const int rb  = (wm + mf*16 + g)*BKP + kk + 2*tig;
                const int rb8 = rb + 8*BKP;
                const uint32_t ah0 = *(const uint32_t*)&ah[rb];
                const uint32_t ah1 = *(const uint32_t*)&ah[rb8];
                const uint32_t ah2 = *(const uint32_t*)&ah[rb + 8];
                const uint32_t ah3 = *(const uint32_t*)&ah[rb8 + 8];
                const uint32_t al0 = *(const uint32_t*)&al[rb];
                const uint32_t al1 = *(const uint32_t*)&al[rb8];
                const uint32_t al2 = *(const uint32_t*)&al[rb + 8];
                const uint32_t al3 = *(const uint32_t*)&al[rb8 + 8];
                #pragma unroll
                for (int nf = 0; nf < 4; nf++) {
                    mma_bf16(acc[mf][nf], ah0,ah1,ah2,ah3, bh0[nf], bh1[nf]);
                    mma_bf16(acc[mf][nf], ah0,ah1,ah2,ah3, bl0[nf], bl1[nf]);
                    mma_bf16(acc[mf][nf], al0,al1,al2,al3, bh0[nf], bh1[nf]);
                }
            }
        }
        buf ^= 1;
    }
}

#define GEMM_SMEM \
    __shared__ __nv_bfloat16 Ah[2*TSZ], Al[2*TSZ], Bh[2*TSZ], Bl[2*TSZ];

// ---------------------------------------------------------------------------
// K1: fused QKV projection.  out[m][n] = x[m] . W[n] + b[n]
// grid (1536/128=12, 3072/128=24); each N-tile lies inside one of Wq/Wk/Wv.
// ---------------------------------------------------------------------------
__global__ void __launch_bounds__(256, 2)
qkv_kernel(const float* __restrict__ x,
           const float* __restrict__ Wq, const float* __restrict__ bq,
           const float* __restrict__ Wk, const float* __restrict__ bk,
           const float* __restrict__ Wv, const float* __restrict__ bv)
{
    GEMM_SMEM
    const int m0 = blockIdx.y * 128;
    const int n0 = blockIdx.x * 128;
    const int which = n0 >> 9;
    const float* W    = (which == 0) ? Wq : (which == 1) ? Wk : Wv;
    const float* bias = (which == 0) ? bq : (which == 1) ? bk : bv;
    float* dst        = (which == 0) ? g_q : (which == 1) ? g_k : g_v;
    const int e0 = n0 & 511;

    float acc[4][4][4] = {};
    mma128_core(x, KIN, m0, KB*KS, W, KIN, e0, KE, KIN, acc, Ah, Al, Bh, Bl);

    const int lane = threadIdx.x & 31, warp = threadIdx.x >> 5;
    const int wm = (warp >> 2) * 64, wn = (warp & 3) * 32;
    const int g = lane >> 2, tig = lane & 3;
    #pragma unroll
    for (int mf = 0; mf < 4; mf++)
        #pragma unroll
        for (int nf = 0; nf < 4; nf++) {
            const int e = e0 + wn + nf*8 + 2*tig;       // even
            const int h = e >> 6, d0 = e & 63;
            const float2 bv2 = make_float2(bias[e], bias[e+1]);
            #pragma unroll
            for (int half = 0; half < 2; half++) {
                const int m = m0 + wm + mf*16 + g + half*8;
                const int b = m / KS, s = m % KS;
                float2 v;
                v.x = acc[mf][nf][half*2+0] + bv2.x;
                v.y = acc[mf][nf][half*2+1] + bv2.y;
                *(float2*)(dst + ((size_t)(b*KH + h)*KS + s)*KD + d0) = v;
            }
        }
}

// ---------------------------------------------------------------------------
// K2: positional projections PK[t] / PQ[t], t in [0,767).
// grid (1024/128=8, 6).
// ---------------------------------------------------------------------------
__global__ void __launch_bounds__(256, 2)
pos_kernel(const float* __restrict__ rel_table,
           const float* __restrict__ Wpk, const float* __restrict__ bpk,
           const float* __restrict__ Wpq, const float* __restrict__ bpq)
{
    GEMM_SMEM
    const int m0 = blockIdx.y * 128;
    const int n0 = blockIdx.x * 128;
    const bool isq = (n0 >= 512);
    const float* W    = isq ? Wpq : Wpk;
    const float* bias = isq ? bpq : bpk;
    float* dst        = isq ? g_pq : g_pk;
    const int e0 = n0 & 511;

    float acc[4][4][4] = {};
    mma128_core(rel_table + (size_t)KRELOFF*KIN, KIN, m0, KT,
                W, KIN, e0, KE, KIN, acc, Ah, Al, Bh, Bl);

    const int lane = threadIdx.x & 31, warp = threadIdx.x >> 5;
    const int wm = (warp >> 2) * 64, wn = (warp & 3) * 32;
    const int g = lane >> 2, tig = lane & 3;
    #pragma unroll
    for (int mf = 0; mf < 4; mf++)
        #pragma unroll
        for (int nf = 0; nf < 4; nf++) {
            const int e = e0 + wn + nf*8 + 2*tig;
            const int h = e >> 6, d0 = e & 63;
            const float2 bv2 = make_float2(bias[e], bias[e+1]);
            #pragma unroll
            for (int half = 0; half < 2; half++) {
                const int t = m0 + wm + mf*16 + g + half*8;
                if (t >= KT) continue;
                float2 v;
                v.x = acc[mf][nf][half*2+0] + bv2.x;
                v.y = acc[mf][nf][half*2+1] + bv2.y;
                *(float2*)(dst + ((size_t)h*KT + t)*KD + d0) = v;
            }
        }
}

// ---------------------------------------------------------------------------
// K3/K4: disentangled score tables with t-window tile skipping.
//   which==0: C2P[bh][i][t] = q[bh][i] . PK[h][t]   window [383-r_max, 766-i0]
//   which==1: P2C[bh][j][t] = k[bh][j] . PQ[h][t]   window [i0, r_max+383]
// grid (6, 3, 64).
// ---------------------------------------------------------------------------
__global__ void __launch_bounds__(256, 2)
disent_kernel(int which)
{
    const int i0 = blockIdx.y * 128;           // row block base (i or j)
    const int t0 = blockIdx.x * 128;
    const int r_max = (i0 + 127 < KS - 1) ? i0 + 127 : KS - 1;
    int t_lo, t_hi;
    if (which == 0) { t_lo = (KS - 1) - r_max;  t_hi = (2*KS - 2) - i0; }
    else            { t_lo = i0;                t_hi = r_max + (KS - 1); }
    if (t0 > t_hi || t0 + 127 < t_lo) return;  // tile never read

    GEMM_SMEM
    const int bh = blockIdx.z;
    const int h  = bh & 7;
    const float* vecs = which ? g_k  : g_q;
    const float* pos  = which ? g_pq : g_pk;
    float*       out  = which ? g_p2c : g_c2p;

    float acc[4][4][4] = {};
    mma128_core(vecs + (size_t)bh*KS*KD, KD, i0, KS,
                pos  + (size_t)h*KT*KD,  KD, t0, KT, KD, acc, Ah, Al, Bh, Bl);

    const int lane = threadIdx.x & 31, warp = threadIdx.x >> 5;
    const int wm = (warp >> 2) * 64, wn = (warp & 3) * 32;
    const int g = lane >> 2, tig = lane & 3;
    #pragma unroll
    for (int mf = 0; mf < 4; mf++)
        #pragma unroll
        for (int half = 0; half < 2; half++) {
            const int i = i0 + wm + mf*16 + g + half*8;
            float* orow = out + ((size_t)bh*KS + i)*KTP;
            #pragma unroll
            for (int nf = 0; nf < 4; nf++) {
                const int t = t0 + wn + nf*8 + 2*tig;   // even, < KTP
                float2 v;
                v.x = acc[mf][nf][half*2+0];
                v.y = acc[mf][nf][half*2+1];
                *(float2*)(orow + t) = v;
            }
        }
}

// ---------------------------------------------------------------------------
// 64x64 tile scalar core used inside the attention kernel.
// ---------------------------------------------------------------------------
__device__ __forceinline__ void sgemm64_core(
    const float* __restrict__ A, int lda, int a0, int Mlim,
    const float* __restrict__ Bm, int ldb, int b0, int Nlim,
    int K, float acc[4][4], float* As, float* Bs)
{
    const int tid = threadIdx.x;
    const int tx = tid & 15, ty = tid >> 4;
    const int lr = tid >> 2;
    const int lk = (tid & 3) * 4;

    for (int k0 = 0; k0 < K; k0 += 16) {
        __syncthreads();
        {
            int row = a0 + lr;
            float4 v = make_float4(0.f, 0.f, 0.f, 0.f);
            if (row < Mlim)
                v = *(const float4*)(A + (size_t)row * lda + k0 + lk);
            As[(lk+0)*68 + lr] = v.x; As[(lk+1)*68 + lr] = v.y;
            As[(lk+2)*68 + lr] = v.z; As[(lk+3)*68 + lr] = v.w;
        }
        {
            int row = b0 + lr;
            float4 v = make_float4(0.f, 0.f, 0.f, 0.f);
            if (row < Nlim)
                v = *(const float4*)(Bm + (size_t)row * ldb + k0 + lk);
            Bs[(lk+0)*68 + lr] = v.x; Bs[(lk+1)*68 + lr] = v.y;
            Bs[(lk+2)*68 + lr] = v.z; Bs[(lk+3)*68 + lr] = v.w;
        }
        __syncthreads();
        #pragma unroll
        for (int kk = 0; kk < 16; kk++) {
            float4 a4 = *(const float4*)&As[kk*68 + ty*4];
            float4 b4 = *(const float4*)&Bs[kk*68 + tx*4];
            float av[4] = {a4.x, a4.y, a4.z, a4.w};
            float bv[4] = {b4.x, b4.y, b4.z, b4.w};
            #pragma unroll
            for (int r = 0; r < 4; r++)
                #pragma unroll
                for (int c = 0; c < 4; c++)
                    acc[r][c] = fmaf(av[r], bv[c], acc[r][c]);
        }
    }
}

// ---------------------------------------------------------------------------
// K5: flash attention per (i-tile=64, h, b).  Online softmax over 6 j-tiles.
// logits = (qk + c2p_gather + p2c_gather) * SCALE, mask fill -9e15.
// ---------------------------------------------------------------------------
__global__ void attn_kernel(const int* __restrict__ mask)
{
    __shared__ float As[16*68], Bs[16*68];
    __shared__ float Ss[64*65];
    __shared__ float Vs[64*68];          // aliased: p2c band stage, then V tile
    __shared__ float row_m[64], row_l[64], alpha_s[64];
    __shared__ float red[64*4];
    __shared__ int   msks[64];

    const int i0 = blockIdx.x * 64;
    const int h  = blockIdx.y;
    const int b  = blockIdx.z;
    const int bh = b*KH + h;
    const float* qb   = g_q + (size_t)bh*KS*KD;
    const float* kb   = g_k + (size_t)bh*KS*KD;
    const float* vb   = g_v + (size_t)bh*KS*KD;
    const float* c2pb = g_c2p + (size_t)bh*KS*KTP;
    const float* p2cb = g_p2c + (size_t)bh*KS*KTP;

    const int tid = threadIdx.x;
    const int tx = tid & 15, ty = tid >> 4;
    const int rrow = tid >> 2, q4 = tid & 3;   // softmax: 4 threads per row

    float o[4][4] = {};
    if (tid < 64) { row_m[tid] = -1e30f; row_l[tid] = 0.f; }

    for (int j0 = 0; j0 < KS; j0 += 64) {
        // ---- stage p2c diagonal band into Vs (coalesced per j-row) ----
        __syncthreads();
        {
            const int c = rrow;                     // local j
            const int j = j0 + c;
            const float* src = p2cb + (size_t)j*KTP + (j - i0 + 320);
            #pragma unroll
            for (int xx = 0; xx < 16; xx++) {
                const int x = q4 + xx*4;
                Vs[c*68 + x] = src[x];              // t = j-i0+320+x ; x = 63-r
            }
        }
        if (tid < 64) msks[tid] = mask[b*KS + j0 + tid];
        __syncthreads();

        // ---- init acc with c2p (gmem gather) + p2c (staged) ----
        float acc[4][4];
        #pragma unroll
        for (int r = 0; r < 4; r++) {
            const int i = i0 + ty*4 + r;
            const float* crow = c2pb + (size_t)i*KTP + (j0 - i + 383);
            #pragma unroll
            for (int c = 0; c < 4; c++) {
                const int jl = tx*4 + c;
                acc[r][c] = crow[jl] + Vs[jl*68 + 63 - (ty*4 + r)];
            }
        }

        // ---- c2c: q @ k^T ----
        sgemm64_core(qb, KD, i0, KS, kb, KD, j0, KS, KD, acc, As, Bs);

        // ---- scale + mask, write S tile ----
        #pragma unroll
        for (int r = 0; r < 4; r++)
            #pragma unroll
            for (int c = 0; c < 4; c++) {
                float v = acc[r][c] * KSCALE;
                if (msks[tx*4 + c] == 0) v = -9e15f;
                Ss[(ty*4 + r)*65 + tx*4 + c] = v;
            }
        __syncthreads();

        // ---- online softmax (4 threads/row) ----
        {
            float mx = -1e30f;
            #pragma unroll
            for (int jj = q4*16; jj < q4*16 + 16; jj++)
                mx = fmaxf(mx, Ss[rrow*65 + jj]);
            red[rrow*4 + q4] = mx;
        }
        __syncthreads();
        if (q4 == 0) {
            float mn = fmaxf(fmaxf(red[rrow*4+0], red[rrow*4+1]),
                             fmaxf(red[rrow*4+2], red[rrow*4+3]));
            mn = fmaxf(mn, row_m[rrow]);
            alpha_s[rrow] = __expf(row_m[rrow] - mn);
            row_m[rrow] = mn;
        }
        __syncthreads();
        {
            const float mn = row_m[rrow];
            float s = 0.f;
            #pragma unroll
            for (int jj = q4*16; jj < q4*16 + 16; jj++) {
                float p = __expf(Ss[rrow*65 + jj] - mn);
                Ss[rrow*65 + jj] = p;
                s += p;
            }
            red[rrow*4 + q4] = s;
        }
        __syncthreads();
        if (q4 == 0)
            row_l[rrow] = row_l[rrow]*alpha_s[rrow]
                        + red[rrow*4+0] + red[rrow*4+1] + red[rrow*4+2] + red[rrow*4+3];

        // ---- load V tile into Vs (band consumed already) ----
        {
            const int c = rrow, d0 = q4 * 16;
            const float* src = vb + (size_t)(j0 + c)*KD + d0;
            #pragma unroll
            for (int dd = 0; dd < 16; dd += 4)
                *(float4*)&Vs[c*68 + d0 + dd] = *(const float4*)(src + dd);
        }
        __syncthreads();

        // ---- rescale O, accumulate P @ V ----
        float al[4];
        #pragma unroll
        for (int r = 0; r < 4; r++) al[r] = alpha_s[ty*4 + r];
        #pragma unroll
        for (int r = 0; r < 4; r++)
            #pragma unroll
            for (int c = 0; c < 4; c++) o[r][c] *= al[r];

        #pragma unroll
        for (int jj = 0; jj < 64; jj++) {
            float pv[4];
            #pragma unroll
            for (int r = 0; r < 4; r++) pv[r] = Ss[(ty*4 + r)*65 + jj];
            float4 vv = *(const float4*)&Vs[jj*68 + tx*4];
            float vvv[4] = {vv.x, vv.y, vv.z, vv.w};
            #pragma unroll
            for (int r = 0; r < 4; r++)
                #pragma unroll
                for (int c = 0; c < 4; c++)
                    o[r][c] = fmaf(pv[r], vvv[c], o[r][c]);
        }
    }

    // ---- normalize, store ctx [b][s][h*D+d] ----
    float inv[4];
    #pragma unroll
    for (int r = 0; r < 4; r++) inv[r] = 1.f / row_l[ty*4 + r];
    #pragma unroll
    for (int r = 0; r < 4; r++) {
        const int i = i0 + ty*4 + r;
        #pragma unroll
        for (int c = 0; c < 4; c++)
            g_ctx[((size_t)b*KS + i)*KE + h*KD + tx*4 + c] = o[r][c] * inv[r];
    }
}

// ---------------------------------------------------------------------------
// K6: output projection: out = ctx @ Wo^T + bo
// grid (512/128=4, 3072/128=24).
// ---------------------------------------------------------------------------
__global__ void __launch_bounds__(256, 2)
out_kernel(const float* __restrict__ Wo, const float* __restrict__ bo,
           float* __restrict__ out)
{
    GEMM_SMEM
    const int m0 = blockIdx.y * 128;
    const int n0 = blockIdx.x * 128;

    float acc[4][4][4] = {};
    mma128_core(g_ctx, KE, m0, KB*KS, Wo, KE, n0, KIN, KE, acc, Ah, Al, Bh, Bl);

    const int lane = threadIdx.x & 31, warp = threadIdx.x >> 5;
    const int wm = (warp >> 2) * 64, wn = (warp & 3) * 32;
    const int g = lane >> 2, tig = lane & 3;
    #pragma unroll
    for (int mf = 0; mf < 4; mf++)
        #pragma unroll
        for (int nf = 0; nf < 4; nf++) {
            const int n = n0 + wn + nf*8 + 2*tig;
            const float2 bv2 = make_float2(bo[n], bo[n+1]);
            #pragma unroll
            for (int half = 0; half < 2; half++) {
                const int m = m0 + wm + mf*16 + g + half*8;
                float2 v;
                v.x = acc[mf][nf][half*2+0] + bv2.x;
                v.y = acc[mf][nf][half*2+1] + bv2.y;
                *(float2*)(out + (size_t)m*KIN + n) = v;
            }
        }
}

// ---------------------------------------------------------------------------
extern "C" void kernel_launch(void* const* d_in, const int* in_sizes, int n_in,
                              void* d_out, int out_size)
{
    const float* x    = (const float*)d_in[0];
    const int*   mask = (const int*)  d_in[1];
    const float* Wq   = (const float*)d_in[2];
    const float* bq   = (const float*)d_in[3];
    const float* Wk   = (const float*)d_in[4];
    const float* bk   = (const float*)d_in[5];
    const float* Wv   = (const float*)d_in[6];
    const float* bv   = (const float*)d_in[7];
    const float* rel  = (const float*)d_in[8];
    const float* Wpk  = (const float*)d_in[9];
    const float* bpk  = (const float*)d_in[10];
    const float* Wpq  = (const float*)d_in[11];
    const float* bpq  = (const float*)d_in[12];
    const float* Wo   = (const float*)d_in[13];
    const float* bo   = (const float*)d_in[14];

    dim3 thr(256);
    qkv_kernel   <<<dim3(1536/128, (KB*KS)/128), thr>>>(x, Wq, bq, Wk, bk, Wv, bv);
    pos_kernel   <<<dim3(1024/128, (KT + 127)/128), thr>>>(rel, Wpk, bpk, Wpq, bpq);
    disent_kernel<<<dim3((KT + 127)/128, KS/128, KB*KH), thr>>>(0);
    disent_kernel<<<dim3((KT + 127)/128, KS/128, KB*KH), thr>>>(1);
    attn_kernel  <<<dim3(KS/64, KH, KB), thr>>>(mask);
    out_kernel   <<<dim3(KIN/128, (KB*KS)/128), thr>>>(Wo, bo, (float*)d_out);
}

// round 12
// speedup vs baseline: 1.0646x; 1.0646x over previous
#include <cuda_runtime.h>
#include <cuda_bf16.h>
#include <cstdint>

// ---------------------------------------------------------------------------
// DeBERTa-style disentangled attention.
// B=8 S=384 IN=512 E=512 H=8 D=64, rel offsets t in [0,767), table row t+128.
// R12: R11 with the ldmatrix B-operand fixed to NON-trans (smem [n][k]
//      k-contiguous is already col-major (k,n); .trans scrambled fragments
//      -> rel_err 1.4). A: ldmatrix.x4; B: ldmatrix.x2. bf16 m16n8k16 3-term.
// ---------------------------------------------------------------------------

#define KB 8
#define KS 384
#define KIN 512
#define KE 512
#define KH 8
#define KD 64
#define KT 767            // 2*S-1 (logical)
#define KTP 768           // padded row stride for c2p/p2c scratch
#define KRELOFF 128       // table row = t + 128
#define KSCALE 0.07216878364870323f   // 1/sqrt(64*3)

#define BKP 40            // bf16 smem row stride (elems) = 80B -> conflict-free
#define TSZ (128*BKP)     // one tile buffer (elems)

__device__ float g_q[KB*KH*KS*KD];
__device__ float g_k[KB*KH*KS*KD];
__device__ float g_v[KB*KH*KS*KD];
__device__ float g_pk[KH*KT*KD];
__device__ float g_pq[KH*KT*KD];
__device__ float g_c2p[(size_t)KB*KH*KS*KTP];
__device__ float g_p2c[(size_t)KB*KH*KS*KTP];
__device__ float g_ctx[KB*KS*KE];

// ---------------------------------------------------------------------------
// bf16 / mma helpers
// ---------------------------------------------------------------------------
__device__ __forceinline__ void bsplit(float x, __nv_bfloat16& h, __nv_bfloat16& l)
{
    h = __float2bfloat16_rn(x);
    l = __float2bfloat16_rn(x - __bfloat162float(h));
}

__device__ __forceinline__ uint32_t pack2(__nv_bfloat16 a, __nv_bfloat16 b)
{
    __nv_bfloat162 t(a, b);
    return *reinterpret_cast<uint32_t*>(&t);
}

__device__ __forceinline__ void mma_bf16(float* d,
    uint32_t a0, uint32_t a1, uint32_t a2, uint32_t a3,
    uint32_t b0, uint32_t b1)
{
    asm("mma.sync.aligned.m16n8k16.row.col.f32.bf16.bf16.f32 "
        "{%0,%1,%2,%3}, {%4,%5,%6,%7}, {%8,%9}, {%0,%1,%2,%3};"
        : "+f"(d[0]), "+f"(d[1]), "+f"(d[2]), "+f"(d[3])
        : "r"(a0), "r"(a1), "r"(a2), "r"(a3), "r"(b0), "r"(b1));
}

__device__ __forceinline__ void ldsm_x4(uint32_t& r0, uint32_t& r1,
                                        uint32_t& r2, uint32_t& r3, uint32_t addr)
{
    asm volatile("ldmatrix.sync.aligned.m8n8.x4.shared.b16 {%0,%1,%2,%3}, [%4];"
        : "=r"(r0), "=r"(r1), "=r"(r2), "=r"(r3) : "r"(addr));
}

__device__ __forceinline__ void ldsm_x2(uint32_t& r0, uint32_t& r1, uint32_t addr)
{
    asm volatile("ldmatrix.sync.aligned.m8n8.x2.shared.b16 {%0,%1}, [%2];"
        : "=r"(r0), "=r"(r1) : "r"(addr));
}

// ---------------------------------------------------------------------------
// 128x128 tile GEMM core, 256 threads (8 warps), BK=32, bf16 3-term mma
// (Ah*Bh + Ah*Bl + Al*Bh).  C = A @ Bm^T, A:[Mlim x lda], Bm:[Nlim x ldb]
// row-major (k contiguous).  Warp (warp>>2)*64 x (warp&3)*32 sub-tile:
// 4 m-frags (m16) x 4 n-frags (n8).  Loader splits f32 -> bf16 hi/lo once
// into smem [row][k] (stride BKP=40).  Fragments via ldmatrix:
//   A x4: lane addr row = wm+mf*16+(lane&15), koff = kk+(lane>>4)*8
//         -> m0..m3 = (rows0-7,k0)(rows8-15,k0)(rows0-7,k8)(rows8-15,k8) = a0..a3
//   B x2 (non-trans): lane addr row = wn+nf*8+(lane&7), koff = kk+((lane>>3)&1)*8
//         smem [n][k] k-contig == col-major (k,n); lane l gets B[n=l/4][k=2(l%4)]
//         = b0 spec exactly; second matrix (k+8) = b1.
// K must be a multiple of 32.  D frag: c0=(g,2tig) c1=+1 c2=(g+8,2tig) c3=+1.
// ---------------------------------------------------------------------------
__device__ __forceinline__ void mma128_core(
    const float* __restrict__ A, int lda, int a0r, int Mlim,
    const float* __restrict__ Bm, int ldb, int b0r, int Nlim,
    int K, float acc[4][4][4],
    __nv_bfloat16* Ah, __nv_bfloat16* Al,
    __nv_bfloat16* Bh, __nv_bfloat16* Bl)
{
    const int tid = threadIdx.x;
    const int lane = tid & 31, warp = tid >> 5;
    const int wm = (warp >> 2) * 64;
    const int wn = (warp & 3) * 32;
    const int lrow = tid >> 3;         // 0..31
    const int lk = (tid & 7) * 4;      // 0..28

    // ldmatrix per-lane base addresses (bytes, shared space)
    const int rA = lane & 15, kA = (lane >> 4) * 8;
    const int rB = lane & 7,  kB = ((lane >> 3) & 1) * 8;
    const uint32_t aHb = (uint32_t)__cvta_generic_to_shared(Ah) + ((wm + rA)*BKP + kA)*2;
    const uint32_t aLb = (uint32_t)__cvta_generic_to_shared(Al) + ((wm + rA)*BKP + kA)*2;
    const uint32_t bHb = (uint32_t)__cvta_generic_to_shared(Bh) + ((wn + rB)*BKP + kB)*2;
    const uint32_t bLb = (uint32_t)__cvta_generic_to_shared(Bl) + ((wn + rB)*BKP + kB)*2;

    for (int k0 = 0; k0 < K; k0 += 32) {
        __syncthreads();
        #pragma unroll
        for (int h4 = 0; h4 < 4; h4++) {
            const int row = lrow + h4 * 32;
            {
                const int ar = a0r + row;
                float4 v = make_float4(0.f, 0.f, 0.f, 0.f);
                if (ar < Mlim)
                    v = *(const float4*)(A + (size_t)ar * lda + k0 + lk);
                __nv_bfloat16 hx,hy,hz,hw, lx,ly,lz,lw;
                bsplit(v.x,hx,lx); bsplit(v.y,hy,ly);
                bsplit(v.z,hz,lz); bsplit(v.w,hw,lw);
                *(uint2*)&Ah[row*BKP + lk] = make_uint2(pack2(hx,hy), pack2(hz,hw));
                *(uint2*)&Al[row*BKP + lk] = make_uint2(pack2(lx,ly), pack2(lz,lw));
            }
            {
                const int br = b0r + row;
                float4 v = make_float4(0.f, 0.f, 0.f, 0.f);
                if (br < Nlim)
                    v = *(const float4*)(Bm + (size_t)br * ldb + k0 + lk);
                __nv_bfloat16 hx,hy,hz,hw, lx,ly,lz,lw;
                bsplit(v.x,hx,lx); bsplit(v.y,hy,ly);
                bsplit(v.z,hz,lz); bsplit(v.w,hw,lw);
                *(uint2*)&Bh[row*BKP + lk] = make_uint2(pack2(hx,hy), pack2(hz,hw));
                *(uint2*)&Bl[row*BKP + lk] = make_uint2(pack2(lx,ly), pack2(lz,lw));
            }
        }
        __syncthreads();
        #pragma unroll
        for (int kk = 0; kk < 32; kk += 16) {
            uint32_t bh_[4][2], bl_[4][2];
            #pragma unroll
            for (int nf = 0; nf < 4; nf++) {
                const uint32_t boff = (uint32_t)(nf*8*BKP + kk) * 2;
                ldsm_x2(bh_[nf][0], bh_[nf][1], bHb + boff);
                ldsm_x2(bl_[nf][0], bl_[nf][1], bLb + boff);
            }
            #pragma unroll
            for (int mf = 0; mf < 4; mf++) {
                const uint32_t aoff = (uint32_t)(mf*16*BKP + kk) * 2;
                uint32_t ah0,ah1,ah2,ah3, al0,al1,al2,al3;
                ldsm_x4(ah0,ah1,ah2,ah3, aHb + aoff);
                ldsm_x4(al0,al1,al2,al3, aLb + aoff);
                #pragma unroll
                for (int nf = 0; nf < 4; nf++) {
                    mma_bf16(acc[mf][nf], ah0,ah1,ah2,ah3, bh_[nf][0], bh_[nf][1]);
                    mma_bf16(acc[mf][nf], ah0,ah1,ah2,ah3, bl_[nf][0], bl_[nf][1]);
                    mma_bf16(acc[mf][nf], al0,al1,al2,al3, bh_[nf][0], bh_[nf][1]);
                }
            }
        }
    }
}

#define GEMM_SMEM \
    __shared__ __nv_bfloat16 Ah[TSZ], Al[TSZ], Bh[TSZ], Bl[TSZ];

// ---------------------------------------------------------------------------
// K1: fused QKV projection.  out[m][n] = x[m] . W[n] + b[n]
// grid (1536/128=12, 3072/128=24); each N-tile lies inside one of Wq/Wk/Wv.
// ---------------------------------------------------------------------------
__global__ void __launch_bounds__(256, 2)
qkv_kernel(const float* __restrict__ x,
           const float* __restrict__ Wq, const float* __restrict__ bq,
           const float* __restrict__ Wk, const float* __restrict__ bk,
           const float* __restrict__ Wv, const float* __restrict__ bv)
{
    GEMM_SMEM
    const int m0 = blockIdx.y * 128;
    const int n0 = blockIdx.x * 128;
    const int which = n0 >> 9;
    const float* W    = (which == 0) ? Wq : (which == 1) ? Wk : Wv;
    const float* bias = (which == 0) ? bq : (which == 1) ? bk : bv;
    float* dst        = (which == 0) ? g_q : (which == 1) ? g_k : g_v;
    const int e0 = n0 & 511;

    float acc[4][4][4] = {};
    mma128_core(x, KIN, m0, KB*KS, W, KIN, e0, KE, KIN, acc, Ah, Al, Bh, Bl);

    const int lane = threadIdx.x & 31, warp = threadIdx.x >> 5;
    const int wm = (warp >> 2) * 64, wn = (warp & 3) * 32;
    const int g = lane >> 2, tig = lane & 3;
    #pragma unroll
    for (int mf = 0; mf < 4; mf++)
        #pragma unroll
        for (int nf = 0; nf < 4; nf++) {
            const int e = e0 + wn + nf*8 + 2*tig;       // even
            const int h = e >> 6, d0 = e & 63;
            const float2 bv2 = make_float2(bias[e], bias[e+1]);
            #pragma unroll
            for (int half = 0; half < 2; half++) {
                const int m = m0 + wm + mf*16 + g + half*8;
                const int b = m / KS, s = m % KS;
                float2 v;
                v.x = acc[mf][nf][half*2+0] + bv2.x;
                v.y = acc[mf][nf][half*2+1] + bv2.y;
                *(float2*)(dst + ((size_t)(b*KH + h)*KS + s)*KD + d0) = v;
            }
        }
}

// ---------------------------------------------------------------------------
// K2: positional projections PK[t] / PQ[t], t in [0,767).
// grid (1024/128=8, 6).
// ---------------------------------------------------------------------------
__global__ void __launch_bounds__(256, 2)
pos_kernel(const float* __restrict__ rel_table,
           const float* __restrict__ Wpk, const float* __restrict__ bpk,
           const float* __restrict__ Wpq, const float* __restrict__ bpq)
{
    GEMM_SMEM
    const int m0 = blockIdx.y * 128;
    const int n0 = blockIdx.x * 128;
    const bool isq = (n0 >= 512);
    const float* W    = isq ? Wpq : Wpk;
    const float* bias = isq ? bpq : bpk;
    float* dst        = isq ? g_pq : g_pk;
    const int e0 = n0 & 511;

    float acc[4][4][4] = {};
    mma128_core(rel_table + (size_t)KRELOFF*KIN, KIN, m0, KT,
                W, KIN, e0, KE, KIN, acc, Ah, Al, Bh, Bl);

    const int lane = threadIdx.x & 31, warp = threadIdx.x >> 5;
    const int wm = (warp >> 2) * 64, wn = (warp & 3) * 32;
    const int g = lane >> 2, tig = lane & 3;
    #pragma unroll
    for (int mf = 0; mf < 4; mf++)
        #pragma unroll
        for (int nf = 0; nf < 4; nf++) {
            const int e = e0 + wn + nf*8 + 2*tig;
            const int h = e >> 6, d0 = e & 63;
            const float2 bv2 = make_float2(bias[e], bias[e+1]);
            #pragma unroll
            for (int half = 0; half < 2; half++) {
                const int t = m0 + wm + mf*16 + g + half*8;
                if (t >= KT) continue;
                float2 v;
                v.x = acc[mf][nf][half*2+0] + bv2.x;
                v.y = acc[mf][nf][half*2+1] + bv2.y;
                *(float2*)(dst + ((size_t)h*KT + t)*KD + d0) = v;
            }
        }
}

// ---------------------------------------------------------------------------
// K3: disentangled score tables, BOTH passes in one launch (which = z>>6).
//   which==0: C2P[bh][i][t] = q[bh][i] . PK[h][t]   window [383-r_max, 766-i0]
//   which==1: P2C[bh][j][t] = k[bh][j] . PQ[h][t]   window [i0, r_max+383]
// grid (6, 3, 128).
// ---------------------------------------------------------------------------
__global__ void __launch_bounds__(256, 2)
disent_kernel()
{
    const int which = blockIdx.z >> 6;
    const int bh = blockIdx.z & 63;
    const int i0 = blockIdx.y * 128;           // row block base (i or j)
    const int t0 = blockIdx.x * 128;
    const int r_max = (i0 + 127 < KS - 1) ? i0 + 127 : KS - 1;
    int t_lo, t_hi;
    if (which == 0) { t_lo = (KS - 1) - r_max;  t_hi = (2*KS - 2) - i0; }
    else            { t_lo = i0;                t_hi = r_max + (KS - 1); }
    if (t0 > t_hi || t0 + 127 < t_lo) return;  // tile never read

    GEMM_SMEM
    const int h  = bh & 7;
    const float* vecs = which ? g_k  : g_q;
    const float* pos  = which ? g_pq : g_pk;
    float*       out  = which ? g_p2c : g_c2p;

    float acc[4][4][4] = {};
    mma128_core(vecs + (size_t)bh*KS*KD, KD, i0, KS,
                pos  + (size_t)h*KT*KD,  KD, t0, KT, KD, acc, Ah, Al, Bh, Bl);

    const int lane = threadIdx.x & 31, warp = threadIdx.x >> 5;
    const int wm = (warp >> 2) * 64, wn = (warp & 3) * 32;
    const int g = lane >> 2, tig = lane & 3;
    #pragma unroll
    for (int mf = 0; mf < 4; mf++)
        #pragma unroll
        for (int half = 0; half < 2; half++) {
            const int i = i0 + wm + mf*16 + g + half*8;
            float* orow = out + ((size_t)bh*KS + i)*KTP;
            #pragma unroll
            for (int nf = 0; nf < 4; nf++) {
                const int t = t0 + wn + nf*8 + 2*tig;   // even, < KTP
                float2 v;
                v.x = acc[mf][nf][half*2+0];
                v.y = acc[mf][nf][half*2+1];
                *(float2*)(orow + t) = v;
            }
        }
}

// ---------------------------------------------------------------------------
// 64x64 tile scalar core used inside the attention kernel.
// ---------------------------------------------------------------------------
__device__ __forceinline__ void sgemm64_core(
    const float* __restrict__ A, int lda, int a0, int Mlim,
    const float* __restrict__ Bm, int ldb, int b0, int Nlim,
    int K, float acc[4][4], float* As, float* Bs)
{
    const int tid = threadIdx.x;
    const int tx = tid & 15, ty = tid >> 4;
    const int lr = tid >> 2;
    const int lk = (tid & 3) * 4;

    for (int k0 = 0; k0 < K; k0 += 16) {
        __syncthreads();
        {
            int row = a0 + lr;
            float4 v = make_float4(0.f, 0.f, 0.f, 0.f);
            if (row < Mlim)
                v = *(const float4*)(A + (size_t)row * lda + k0 + lk);
            As[(lk+0)*68 + lr] = v.x; As[(lk+1)*68 + lr] = v.y;
            As[(lk+2)*68 + lr] = v.z; As[(lk+3)*68 + lr] = v.w;
        }
        {
            int row = b0 + lr;
            float4 v = make_float4(0.f, 0.f, 0.f, 0.f);
            if (row < Nlim)
                v = *(const float4*)(Bm + (size_t)row * ldb + k0 + lk);
            Bs[(lk+0)*68 + lr] = v.x; Bs[(lk+1)*68 + lr] = v.y;
            Bs[(lk+2)*68 + lr] = v.z; Bs[(lk+3)*68 + lr] = v.w;
        }
        __syncthreads();
        #pragma unroll
        for (int kk = 0; kk < 16; kk++) {
            float4 a4 = *(const float4*)&As[kk*68 + ty*4];
            float4 b4 = *(const float4*)&Bs[kk*68 + tx*4];
            float av[4] = {a4.x, a4.y, a4.z, a4.w};
            float bv[4] = {b4.x, b4.y, b4.z, b4.w};
            #pragma unroll
            for (int r = 0; r < 4; r++)
                #pragma unroll
                for (int c = 0; c < 4; c++)
                    acc[r][c] = fmaf(av[r], bv[c], acc[r][c]);
        }
    }
}

// ---------------------------------------------------------------------------
// K5: flash attention per (i-tile=64, h, b).  Online softmax over 6 j-tiles.
// logits = (qk + c2p_gather + p2c_gather) * SCALE, mask fill -9e15.
// ---------------------------------------------------------------------------
__global__ void attn_kernel(const int* __restrict__ mask)
{
    __shared__ float As[16*68], Bs[16*68];
    __shared__ float Ss[64*65];
    __shared__ float Vs[64*68];          // aliased: p2c band stage, then V tile
    __shared__ float row_m[64], row_l[64], alpha_s[64];
    __shared__ float red[64*4];
    __shared__ int   msks[64];

    const int i0 = blockIdx.x * 64;
    const int h  = blockIdx.y;
    const int b  = blockIdx.z;
    const int bh = b*KH + h;
    const float* qb   = g_q + (size_t)bh*KS*KD;
    const float* kb   = g_k + (size_t)bh*KS*KD;
    const float* vb   = g_v + (size_t)bh*KS*KD;
    const float* c2pb = g_c2p + (size_t)bh*KS*KTP;
    const float* p2cb = g_p2c + (size_t)bh*KS*KTP;

    const int tid = threadIdx.x;
    const int tx = tid & 15, ty = tid >> 4;
    const int rrow = tid >> 2, q4 = tid & 3;   // softmax: 4 threads per row

    float o[4][4] = {};
    if (tid < 64) { row_m[tid] = -1e30f; row_l[tid] = 0.f; }

    for (int j0 = 0; j0 < KS; j0 += 64) {
        // ---- stage p2c diagonal band into Vs (coalesced per j-row) ----
        __syncthreads();
        {
            const int c = rrow;                     // local j
            const int j = j0 + c;
            const float* src = p2cb + (size_t)j*KTP + (j - i0 + 320);
            #pragma unroll
            for (int xx = 0; xx < 16; xx++) {
                const int x = q4 + xx*4;
                Vs[c*68 + x] = src[x];              // t = j-i0+320+x ; x = 63-r
            }
        }
        if (tid < 64) msks[tid] = mask[b*KS + j0 + tid];
        __syncthreads();

        // ---- init acc with c2p (gmem gather) + p2c (staged) ----
        float acc[4][4];
        #pragma unroll
        for (int r = 0; r < 4; r++) {
            const int i = i0 + ty*4 + r;
            const float* crow = c2pb + (size_t)i*KTP + (j0 - i + 383);
            #pragma unroll
            for (int c = 0; c < 4; c++) {
                const int jl = tx*4 + c;
                acc[r][c] = crow[jl] + Vs[jl*68 + 63 - (ty*4 + r)];
            }
        }

        // ---- c2c: q @ k^T ----
        sgemm64_core(qb, KD, i0, KS, kb, KD, j0, KS, KD, acc, As, Bs);

        // ---- scale + mask, write S tile ----
        #pragma unroll
        for (int r = 0; r < 4; r++)
            #pragma unroll
            for (int c = 0; c < 4; c++) {
                float v = acc[r][c] * KSCALE;
                if (msks[tx*4 + c] == 0) v = -9e15f;
                Ss[(ty*4 + r)*65 + tx*4 + c] = v;
            }
        __syncthreads();

        // ---- online softmax (4 threads/row) ----
        {
            float mx = -1e30f;
            #pragma unroll
            for (int jj = q4*16; jj < q4*16 + 16; jj++)
                mx = fmaxf(mx, Ss[rrow*65 + jj]);
            red[rrow*4 + q4] = mx;
        }
        __syncthreads();
        if (q4 == 0) {
            float mn = fmaxf(fmaxf(red[rrow*4+0], red[rrow*4+1]),
                             fmaxf(red[rrow*4+2], red[rrow*4+3]));
            mn = fmaxf(mn, row_m[rrow]);
            alpha_s[rrow] = __expf(row_m[rrow] - mn);
            row_m[rrow] = mn;
        }
        __syncthreads();
        {
            const float mn = row_m[rrow];
            float s = 0.f;
            #pragma unroll
            for (int jj = q4*16; jj < q4*16 + 16; jj++) {
                float p = __expf(Ss[rrow*65 + jj] - mn);
                Ss[rrow*65 + jj] = p;
                s += p;
            }
            red[rrow*4 + q4] = s;
        }
        __syncthreads();
        if (q4 == 0)
            row_l[rrow] = row_l[rrow]*alpha_s[rrow]
                        + red[rrow*4+0] + red[rrow*4+1] + red[rrow*4+2] + red[rrow*4+3];

        // ---- load V tile into Vs (band consumed already) ----
        {
            const int c = rrow, d0 = q4 * 16;
            const float* src = vb + (size_t)(j0 + c)*KD + d0;
            #pragma unroll
            for (int dd = 0; dd < 16; dd += 4)
                *(float4*)&Vs[c*68 + d0 + dd] = *(const float4*)(src + dd);
        }
        __syncthreads();

        // ---- rescale O, accumulate P @ V ----
        float al[4];
        #pragma unroll
        for (int r = 0; r < 4; r++) al[r] = alpha_s[ty*4 + r];
        #pragma unroll
        for (int r = 0; r < 4; r++)
            #pragma unroll
            for (int c = 0; c < 4; c++) o[r][c] *= al[r];

        #pragma unroll
        for (int jj = 0; jj < 64; jj++) {
            float pv[4];
            #pragma unroll
            for (int r = 0; r < 4; r++) pv[r] = Ss[(ty*4 + r)*65 + jj];
            float4 vv = *(const float4*)&Vs[jj*68 + tx*4];
            float vvv[4] = {vv.x, vv.y, vv.z, vv.w};
            #pragma unroll
            for (int r = 0; r < 4; r++)
                #pragma unroll
                for (int c = 0; c < 4; c++)
                    o[r][c] = fmaf(pv[r], vvv[c], o[r][c]);
        }
    }

    // ---- normalize, store ctx [b][s][h*D+d] ----
    float inv[4];
    #pragma unroll
    for (int r = 0; r < 4; r++) inv[r] = 1.f / row_l[ty*4 + r];
    #pragma unroll
    for (int r = 0; r < 4; r++) {
        const int i = i0 + ty*4 + r;
        #pragma unroll
        for (int c = 0; c < 4; c++)
            g_ctx[((size_t)b*KS + i)*KE + h*KD + tx*4 + c] = o[r][c] * inv[r];
    }
}

// ---------------------------------------------------------------------------
// K6: output projection: out = ctx @ Wo^T + bo
// grid (512/128=4, 3072/128=24).
// ---------------------------------------------------------------------------
__global__ void __launch_bounds__(256, 2)
out_kernel(const float* __restrict__ Wo, const float* __restrict__ bo,
           float* __restrict__ out)
{
    GEMM_SMEM
    const int m0 = blockIdx.y * 128;
    const int n0 = blockIdx.x * 128;

    float acc[4][4][4] = {};
    mma128_core(g_ctx, KE, m0, KB*KS, Wo, KE, n0, KIN, KE, acc, Ah, Al, Bh, Bl);

    const int lane = threadIdx.x & 31, warp = threadIdx.x >> 5;
    const int wm = (warp >> 2) * 64, wn = (warp & 3) * 32;
    const int g = lane >> 2, tig = lane & 3;
    #pragma unroll
    for (int mf = 0; mf < 4; mf++)
        #pragma unroll
        for (int nf = 0; nf < 4; nf++) {
            const int n = n0 + wn + nf*8 + 2*tig;
            const float2 bv2 = make_float2(bo[n], bo[n+1]);
            #pragma unroll
            for (int half = 0; half < 2; half++) {
                const int m = m0 + wm + mf*16 + g + half*8;
                float2 v;
                v.x = acc[mf][nf][half*2+0] + bv2.x;
                v.y = acc[mf][nf][half*2+1] + bv2.y;
                *(float2*)(out + (size_t)m*KIN + n) = v;
            }
        }
}

// ---------------------------------------------------------------------------
extern "C" void kernel_launch(void* const* d_in, const int* in_sizes, int n_in,
                              void* d_out, int out_size)
{
    const float* x    = (const float*)d_in[0];
    const int*   mask = (const int*)  d_in[1];
    const float* Wq   = (const float*)d_in[2];
    const float* bq   = (const float*)d_in[3];
    const float* Wk   = (const float*)d_in[4];
    const float* bk   = (const float*)d_in[5];
    const float* Wv   = (const float*)d_in[6];
    const float* bv   = (const float*)d_in[7];
    const float* rel  = (const float*)d_in[8];
    const float* Wpk  = (const float*)d_in[9];
    const float* bpk  = (const float*)d_in[10];
    const float* Wpq  = (const float*)d_in[11];
    const float* bpq  = (const float*)d_in[12];
    const float* Wo   = (const float*)d_in[13];
    const float* bo   = (const float*)d_in[14];

    dim3 thr(256);
    qkv_kernel   <<<dim3(1536/128, (KB*KS)/128), thr>>>(x, Wq, bq, Wk, bk, Wv, bv);
    pos_kernel   <<<dim3(1024/128, (KT + 127)/128), thr>>>(rel, Wpk, bpk, Wpq, bpq);
    disent_kernel<<<dim3((KT + 127)/128, KS/128, 2*KB*KH), thr>>>();
    attn_kernel  <<<dim3(KS/64, KH, KB), thr>>>(mask);
    out_kernel   <<<dim3(KIN/128, (KB*KS)/128), thr>>>(Wo, bo, (float*)d_out);
}

// round 13
// speedup vs baseline: 1.2831x; 1.2052x over previous
#include <cuda_runtime.h>
#include <cuda_bf16.h>
#include <cstdint>

// ---------------------------------------------------------------------------
// DeBERTa-style disentangled attention.
// B=8 S=384 IN=512 E=512 H=8 D=64, rel offsets t in [0,767), table row t+128.
// R13: attention kernel moved to bf16 tensor cores:
//      c2c = Q@K^T (A x4 ldmatrix, B non-trans x2 — R12-verified pattern),
//      P@V with V via ldmatrix .trans (row-major [j][d] = k-major), P split
//      2-term. Register-fragment softmax with shfl reductions. GEMM kernels
//      unchanged from R12.
// ---------------------------------------------------------------------------

#define KB 8
#define KS 384
#define KIN 512
#define KE 512
#define KH 8
#define KD 64
#define KT 767            // 2*S-1 (logical)
#define KTP 768           // padded row stride for c2p/p2c scratch
#define KRELOFF 128       // table row = t + 128
#define KSCALE 0.07216878364870323f   // 1/sqrt(64*3)

#define BKP 40            // bf16 smem row stride (elems) = 80B -> conflict-free
#define TSZ (128*BKP)     // one tile buffer (elems)
#define ASP 72            // attn bf16 smem row stride (elems) = 144B -> conflict-free

__device__ float g_q[KB*KH*KS*KD];
__device__ float g_k[KB*KH*KS*KD];
__device__ float g_v[KB*KH*KS*KD];
__device__ float g_pk[KH*KT*KD];
__device__ float g_pq[KH*KT*KD];
__device__ float g_c2p[(size_t)KB*KH*KS*KTP];
__device__ float g_p2c[(size_t)KB*KH*KS*KTP];
__device__ float g_ctx[KB*KS*KE];

// ---------------------------------------------------------------------------
// bf16 / mma helpers
// ---------------------------------------------------------------------------
__device__ __forceinline__ void bsplit(float x, __nv_bfloat16& h, __nv_bfloat16& l)
{
    h = __float2bfloat16_rn(x);
    l = __float2bfloat16_rn(x - __bfloat162float(h));
}

__device__ __forceinline__ uint32_t pack2(__nv_bfloat16 a, __nv_bfloat16 b)
{
    __nv_bfloat162 t(a, b);
    return *reinterpret_cast<uint32_t*>(&t);
}

__device__ __forceinline__ void mma_bf16(float* d,
    uint32_t a0, uint32_t a1, uint32_t a2, uint32_t a3,
    uint32_t b0, uint32_t b1)
{
    asm("mma.sync.aligned.m16n8k16.row.col.f32.bf16.bf16.f32 "
        "{%0,%1,%2,%3}, {%4,%5,%6,%7}, {%8,%9}, {%0,%1,%2,%3};"
        : "+f"(d[0]), "+f"(d[1]), "+f"(d[2]), "+f"(d[3])
        : "r"(a0), "r"(a1), "r"(a2), "r"(a3), "r"(b0), "r"(b1));
}

__device__ __forceinline__ void ldsm_x4(uint32_t& r0, uint32_t& r1,
                                        uint32_t& r2, uint32_t& r3, uint32_t addr)
{
    asm volatile("ldmatrix.sync.aligned.m8n8.x4.shared.b16 {%0,%1,%2,%3}, [%4];"
        : "=r"(r0), "=r"(r1), "=r"(r2), "=r"(r3) : "r"(addr));
}

__device__ __forceinline__ void ldsm_x2(uint32_t& r0, uint32_t& r1, uint32_t addr)
{
    asm volatile("ldmatrix.sync.aligned.m8n8.x2.shared.b16 {%0,%1}, [%2];"
        : "=r"(r0), "=r"(r1) : "r"(addr));
}

__device__ __forceinline__ void ldsm_x2t(uint32_t& r0, uint32_t& r1, uint32_t addr)
{
    asm volatile("ldmatrix.sync.aligned.m8n8.x2.trans.shared.b16 {%0,%1}, [%2];"
        : "=r"(r0), "=r"(r1) : "r"(addr));
}

__device__ __forceinline__ void split4(float4 v, __nv_bfloat16* H, __nv_bfloat16* L, int off)
{
    __nv_bfloat16 hx,hy,hz,hw, lx,ly,lz,lw;
    bsplit(v.x,hx,lx); bsplit(v.y,hy,ly);
    bsplit(v.z,hz,lz); bsplit(v.w,hw,lw);
    *(uint2*)&H[off] = make_uint2(pack2(hx,hy), pack2(hz,hw));
    *(uint2*)&L[off] = make_uint2(pack2(lx,ly), pack2(lz,lw));
}

// ---------------------------------------------------------------------------
// 128x128 tile GEMM core (unchanged from R12 — verified).
// ---------------------------------------------------------------------------
__device__ __forceinline__ void mma128_core(
    const float* __restrict__ A, int lda, int a0r, int Mlim,
    const float* __restrict__ Bm, int ldb, int b0r, int Nlim,
    int K, float acc[4][4][4],
    __nv_bfloat16* Ah, __nv_bfloat16* Al,
    __nv_bfloat16* Bh, __nv_bfloat16* Bl)
{
    const int tid = threadIdx.x;
    const int lane = tid & 31, warp = tid >> 5;
    const int wm = (warp >> 2) * 64;
    const int wn = (warp & 3) * 32;
    const int lrow = tid >> 3;         // 0..31
    const int lk = (tid & 7) * 4;      // 0..28

    const int rA = lane & 15, kA = (lane >> 4) * 8;
    const int rB = lane & 7,  kB = ((lane >> 3) & 1) * 8;
    const uint32_t aHb = (uint32_t)__cvta_generic_to_shared(Ah) + ((wm + rA)*BKP + kA)*2;
    const uint32_t aLb = (uint32_t)__cvta_generic_to_shared(Al) + ((wm + rA)*BKP + kA)*2;
    const uint32_t bHb = (uint32_t)__cvta_generic_to_shared(Bh) + ((wn + rB)*BKP + kB)*2;
    const uint32_t bLb = (uint32_t)__cvta_generic_to_shared(Bl) + ((wn + rB)*BKP + kB)*2;

    for (int k0 = 0; k0 < K; k0 += 32) {
        __syncthreads();
        #pragma unroll
        for (int h4 = 0; h4 < 4; h4++) {
            const int row = lrow + h4 * 32;
            {
                const int ar = a0r + row;
                float4 v = make_float4(0.f, 0.f, 0.f, 0.f);
                if (ar < Mlim)
                    v = *(const float4*)(A + (size_t)ar * lda + k0 + lk);
                split4(v, Ah, Al, row*BKP + lk);
            }
            {
                const int br = b0r + row;
                float4 v = make_float4(0.f, 0.f, 0.f, 0.f);
                if (br < Nlim)
                    v = *(const float4*)(Bm + (size_t)br * ldb + k0 + lk);
                split4(v, Bh, Bl, row*BKP + lk);
            }
        }
        __syncthreads();
        #pragma unroll
        for (int kk = 0; kk < 32; kk += 16) {
            uint32_t bh_[4][2], bl_[4][2];
            #pragma unroll
            for (int nf = 0; nf < 4; nf++) {
                const uint32_t boff = (uint32_t)(nf*8*BKP + kk) * 2;
                ldsm_x2(bh_[nf][0], bh_[nf][1], bHb + boff);
                ldsm_x2(bl_[nf][0], bl_[nf][1], bLb + boff);
            }
            #pragma unroll
            for (int mf = 0; mf < 4; mf++) {
                const uint32_t aoff = (uint32_t)(mf*16*BKP + kk) * 2;
                uint32_t ah0,ah1,ah2,ah3, al0,al1,al2,al3;
                ldsm_x4(ah0,ah1,ah2,ah3, aHb + aoff);
                ldsm_x4(al0,al1,al2,al3, aLb + aoff);
                #pragma unroll
                for (int nf = 0; nf < 4; nf++) {
                    mma_bf16(acc[mf][nf], ah0,ah1,ah2,ah3, bh_[nf][0], bh_[nf][1]);
                    mma_bf16(acc[mf][nf], ah0,ah1,ah2,ah3, bl_[nf][0], bl_[nf][1]);
                    mma_bf16(acc[mf][nf], al0,al1,al2,al3, bh_[nf][0], bh_[nf][1]);
                }
            }
        }
    }
}

#define GEMM_SMEM \
    __shared__ __nv_bfloat16 Ah[TSZ], Al[TSZ], Bh[TSZ], Bl[TSZ];

// ---------------------------------------------------------------------------
// K1: fused QKV projection.
// ---------------------------------------------------------------------------
__global__ void __launch_bounds__(256, 2)
qkv_kernel(const float* __restrict__ x,
           const float* __restrict__ Wq, const float* __restrict__ bq,
           const float* __restrict__ Wk, const float* __restrict__ bk,
           const float* __restrict__ Wv, const float* __restrict__ bv)
{
    GEMM_SMEM
    const int m0 = blockIdx.y * 128;
    const int n0 = blockIdx.x * 128;
    const int which = n0 >> 9;
    const float* W    = (which == 0) ? Wq : (which == 1) ? Wk : Wv;
    const float* bias = (which == 0) ? bq : (which == 1) ? bk : bv;
    float* dst        = (which == 0) ? g_q : (which == 1) ? g_k : g_v;
    const int e0 = n0 & 511;

    float acc[4][4][4] = {};
    mma128_core(x, KIN, m0, KB*KS, W, KIN, e0, KE, KIN, acc, Ah, Al, Bh, Bl);

    const int lane = threadIdx.x & 31, warp = threadIdx.x >> 5;
    const int wm = (warp >> 2) * 64, wn = (warp & 3) * 32;
    const int g = lane >> 2, tig = lane & 3;
    #pragma unroll
    for (int mf = 0; mf < 4; mf++)
        #pragma unroll
        for (int nf = 0; nf < 4; nf++) {
            const int e = e0 + wn + nf*8 + 2*tig;       // even
            const int h = e >> 6, d0 = e & 63;
            const float2 bv2 = make_float2(bias[e], bias[e+1]);
            #pragma unroll
            for (int half = 0; half < 2; half++) {
                const int m = m0 + wm + mf*16 + g + half*8;
                const int b = m / KS, s = m % KS;
                float2 v;
                v.x = acc[mf][nf][half*2+0] + bv2.x;
                v.y = acc[mf][nf][half*2+1] + bv2.y;
                *(float2*)(dst + ((size_t)(b*KH + h)*KS + s)*KD + d0) = v;
            }
        }
}

// ---------------------------------------------------------------------------
// K2: positional projections PK[t] / PQ[t].
// ---------------------------------------------------------------------------
__global__ void __launch_bounds__(256, 2)
pos_kernel(const float* __restrict__ rel_table,
           const float* __restrict__ Wpk, const float* __restrict__ bpk,
           const float* __restrict__ Wpq, const float* __restrict__ bpq)
{
    GEMM_SMEM
    const int m0 = blockIdx.y * 128;
    const int n0 = blockIdx.x * 128;
    const bool isq = (n0 >= 512);
    const float* W    = isq ? Wpq : Wpk;
    const float* bias = isq ? bpq : bpk;
    float* dst        = isq ? g_pq : g_pk;
    const int e0 = n0 & 511;

    float acc[4][4][4] = {};
    mma128_core(rel_table + (size_t)KRELOFF*KIN, KIN, m0, KT,
                W, KIN, e0, KE, KIN, acc, Ah, Al, Bh, Bl);

    const int lane = threadIdx.x & 31, warp = threadIdx.x >> 5;
    const int wm = (warp >> 2) * 64, wn = (warp & 3) * 32;
    const int g = lane >> 2, tig = lane & 3;
    #pragma unroll
    for (int mf = 0; mf < 4; mf++)
        #pragma unroll
        for (int nf = 0; nf < 4; nf++) {
            const int e = e0 + wn + nf*8 + 2*tig;
            const int h = e >> 6, d0 = e & 63;
            const float2 bv2 = make_float2(bias[e], bias[e+1]);
            #pragma unroll
            for (int half = 0; half < 2; half++) {
                const int t = m0 + wm + mf*16 + g + half*8;
                if (t >= KT) continue;
                float2 v;
                v.x = acc[mf][nf][half*2+0] + bv2.x;
                v.y = acc[mf][nf][half*2+1] + bv2.y;
                *(float2*)(dst + ((size_t)h*KT + t)*KD + d0) = v;
            }
        }
}

// ---------------------------------------------------------------------------
// K3: disentangled score tables, both passes in one launch (which = z>>6).
// ---------------------------------------------------------------------------
__global__ void __launch_bounds__(256, 2)
disent_kernel()
{
    const int which = blockIdx.z >> 6;
    const int bh = blockIdx.z & 63;
    const int i0 = blockIdx.y * 128;
    const int t0 = blockIdx.x * 128;
    const int r_max = (i0 + 127 < KS - 1) ? i0 + 127 : KS - 1;
    int t_lo, t_hi;
    if (which == 0) { t_lo = (KS - 1) - r_max;  t_hi = (2*KS - 2) - i0; }
    else            { t_lo = i0;                t_hi = r_max + (KS - 1); }
    if (t0 > t_hi || t0 + 127 < t_lo) return;

    GEMM_SMEM
    const int h  = bh & 7;
    const float* vecs = which ? g_k  : g_q;
    const float* pos  = which ? g_pq : g_pk;
    float*       out  = which ? g_p2c : g_c2p;

    float acc[4][4][4] = {};
    mma128_core(vecs + (size_t)bh*KS*KD, KD, i0, KS,
                pos  + (size_t)h*KT*KD,  KD, t0, KT, KD, acc, Ah, Al, Bh, Bl);

    const int lane = threadIdx.x & 31, warp = threadIdx.x >> 5;
    const int wm = (warp >> 2) * 64, wn = (warp & 3) * 32;
    const int g = lane >> 2, tig = lane & 3;
    #pragma unroll
    for (int mf = 0; mf < 4; mf++)
        #pragma unroll
        for (int half = 0; half < 2; half++) {
            const int i = i0 + wm + mf*16 + g + half*8;
            float* orow = out + ((size_t)bh*KS + i)*KTP;
            #pragma unroll
            for (int nf = 0; nf < 4; nf++) {
                const int t = t0 + wn + nf*8 + 2*tig;
                float2 v;
                v.x = acc[mf][nf][half*2+0];
                v.y = acc[mf][nf][half*2+1];
                *(float2*)(orow + t) = v;
            }
        }
}

// ---------------------------------------------------------------------------
// K5: flash attention, bf16 MMA version.  i-tile=64, 8 warps.
// Warp w: rows wm=(w>>1)*16, cols wn=(w&1)*32 -> 1 m16 frag x 4 n8 frags.
// Per j-tile: c2c mma -> logits(+c2p gather, p2c band, scale, mask) ->
// frag softmax (shfl over tig + smem cross-warp combine) -> P split to smem
// -> O rescale -> P@V mma (V via ldmatrix .trans).
// ---------------------------------------------------------------------------
__global__ void __launch_bounds__(256, 2)
attn_kernel(const int* __restrict__ mask)
{
    __shared__ __nv_bfloat16 Qh[64*ASP], Ql[64*ASP];
    __shared__ __nv_bfloat16 KhS[64*ASP], KlS[64*ASP];
    __shared__ __nv_bfloat16 VhS[64*ASP], VlS[64*ASP];
    __shared__ __align__(16) char uni[64*ASP*2*2];   // band [64][68]f  |  Ph,Pl
    __shared__ float pm[2][64];
    __shared__ float row_m[64], row_l[64], alpha_s[64];
    __shared__ int   msks[64];

    float* band = (float*)uni;                               // [64][68]
    __nv_bfloat16* Ph = (__nv_bfloat16*)uni;                 // [64][ASP]
    __nv_bfloat16* Pl = (__nv_bfloat16*)(uni + 64*ASP*2);

    const int i0 = blockIdx.x * 64;
    const int h  = blockIdx.y;
    const int b  = blockIdx.z;
    const int bh = b*KH + h;
    const float* qb   = g_q + (size_t)bh*KS*KD;
    const float* kb   = g_k + (size_t)bh*KS*KD;
    const float* vb   = g_v + (size_t)bh*KS*KD;
    const float* c2pb = g_c2p + (size_t)bh*KS*KTP;
    const float* p2cb = g_p2c + (size_t)bh*KS*KTP;

    const int tid = threadIdx.x;
    const int lane = tid & 31, warp = tid >> 5;
    const int wm = (warp >> 1) * 16;
    const int wnh = warp & 1;
    const int wn = wnh * 32;
    const int g = lane >> 2, tig = lane & 3;
    const int r0 = wm + g, r1 = r0 + 8;

    // ldmatrix lane base offsets (elems)
    const int rA = lane & 15, kA = (lane >> 4) * 8;   // A x4 (rows=m)
    const int rB = lane & 7,  kBo = ((lane >> 3) & 1) * 8;  // B x2 non-trans
    const int rV = lane & 15;                          // B x2 trans (rows=k)

    const uint32_t qhB = (uint32_t)__cvta_generic_to_shared(Qh) + ((wm + rA)*ASP + kA)*2;
    const uint32_t qlB = (uint32_t)__cvta_generic_to_shared(Ql) + ((wm + rA)*ASP + kA)*2;
    const uint32_t khB = (uint32_t)__cvta_generic_to_shared(KhS) + ((wn + rB)*ASP + kBo)*2;
    const uint32_t klB = (uint32_t)__cvta_generic_to_shared(KlS) + ((wn + rB)*ASP + kBo)*2;
    const uint32_t phB = (uint32_t)__cvta_generic_to_shared(Ph) + ((wm + rA)*ASP + kA)*2;
    const uint32_t plB = (uint32_t)__cvta_generic_to_shared(Pl) + ((wm + rA)*ASP + kA)*2;
    const uint32_t vhB = (uint32_t)__cvta_generic_to_shared(VhS) + (rV*ASP + wn)*2;
    const uint32_t vlB = (uint32_t)__cvta_generic_to_shared(VlS) + (rV*ASP + wn)*2;

    // ---- load Q (once), init softmax state ----
    {
        const int row = tid >> 2, kb4 = (tid & 3) * 16;
        const float* src = qb + (size_t)(i0 + row)*KD + kb4;
        #pragma unroll
        for (int qq = 0; qq < 4; qq++)
            split4(*(const float4*)(src + qq*4), Qh, Ql, row*ASP + kb4 + qq*4);
    }
    if (tid < 64) { row_m[tid] = -1e30f; row_l[tid] = 0.f; }

    float o[4][4] = {};

    for (int j0 = 0; j0 < KS; j0 += 64) {
        __syncthreads();   // s0: smem (K,V,band/P) free for reuse
        // ---- stage K, V (split) ----
        {
            const int row = tid >> 2, kb4 = (tid & 3) * 16;
            const float* ks = kb + (size_t)(j0 + row)*KD + kb4;
            const float* vs = vb + (size_t)(j0 + row)*KD + kb4;
            #pragma unroll
            for (int qq = 0; qq < 4; qq++) {
                split4(*(const float4*)(ks + qq*4), KhS, KlS, row*ASP + kb4 + qq*4);
                split4(*(const float4*)(vs + qq*4), VhS, VlS, row*ASP + kb4 + qq*4);
            }
        }
        // ---- stage p2c band: band[jl][x], value for row r is band[jl][63-r] ----
        {
            const int c = tid >> 2, q4 = tid & 3;
            const float* src = p2cb + (size_t)(j0 + c)*KTP + (j0 + c - i0 + 320);
            #pragma unroll
            for (int xx = 0; xx < 16; xx++) {
                const int x = q4 + xx*4;
                band[c*68 + x] = src[x];
            }
        }
        if (tid < 64) msks[tid] = mask[b*KS + j0 + tid];
        __syncthreads();   // s1

        // ---- c2c: Q @ K^T ----
        float acc[4][4] = {};
        #pragma unroll
        for (int kk = 0; kk < 64; kk += 16) {
            uint32_t qh0,qh1,qh2,qh3, ql0,ql1,ql2,ql3;
            ldsm_x4(qh0,qh1,qh2,qh3, qhB + kk*2);
            ldsm_x4(ql0,ql1,ql2,ql3, qlB + kk*2);
            #pragma unroll
            for (int nf = 0; nf < 4; nf++) {
                const uint32_t boff = (uint32_t)(nf*8*ASP + kk)*2;
                uint32_t b0h,b1h, b0l,b1l;
                ldsm_x2(b0h,b1h, khB + boff);
                ldsm_x2(b0l,b1l, klB + boff);
                mma_bf16(acc[nf], qh0,qh1,qh2,qh3, b0h,b1h);
                mma_bf16(acc[nf], qh0,qh1,qh2,qh3, b0l,b1l);
                mma_bf16(acc[nf], ql0,ql1,ql2,ql3, b0h,b1h);
            }
        }

        // ---- logits = (c2c + c2p + p2c)*SCALE, mask; partial row max ----
        const float* c0row = c2pb + (size_t)(i0 + r0)*KTP + (j0 - (i0 + r0) + 383);
        const float* c1row = c2pb + (size_t)(i0 + r1)*KTP + (j0 - (i0 + r1) + 383);
        float m0 = -1e30f, m1 = -1e30f;
        #pragma unroll
        for (int nf = 0; nf < 4; nf++) {
            const int jl = wn + nf*8 + 2*tig;
            float v0 = (acc[nf][0] + c0row[jl]   + band[jl*68     + 63 - r0]) * KSCALE;
            float v1 = (acc[nf][1] + c0row[jl+1] + band[(jl+1)*68 + 63 - r0]) * KSCALE;
            float v2 = (acc[nf][2] + c1row[jl]   + band[jl*68     + 63 - r1]) * KSCALE;
            float v3 = (acc[nf][3] + c1row[jl+1] + band[(jl+1)*68 + 63 - r1]) * KSCALE;
            if (msks[jl]   == 0) { v0 = -9e15f; v2 = -9e15f; }
            if (msks[jl+1] == 0) { v1 = -9e15f; v3 = -9e15f; }
            acc[nf][0] = v0; acc[nf][1] = v1; acc[nf][2] = v2; acc[nf][3] = v3;
            m0 = fmaxf(m0, fmaxf(v0, v1));
            m1 = fmaxf(m1, fmaxf(v2, v3));
        }
        m0 = fmaxf(m0, __shfl_xor_sync(0xffffffffu, m0, 1));
        m0 = fmaxf(m0, __shfl_xor_sync(0xffffffffu, m0, 2));
        m1 = fmaxf(m1, __shfl_xor_sync(0xffffffffu, m1, 1));
        m1 = fmaxf(m1, __shfl_xor_sync(0xffffffffu, m1, 2));
        if (tig == 0) { pm[wnh][r0] = m0; pm[wnh][r1] = m1; }
        __syncthreads();   // s2
        if (tid < 64) {
            float M = fmaxf(row_m[tid], fmaxf(pm[0][tid], pm[1][tid]));
            alpha_s[tid] = __expf(row_m[tid] - M);
            row_m[tid] = M;
        }
        __syncthreads();   // s3

        // ---- p = exp(l - M); partial sums; split P to smem ----
        const float M0 = row_m[r0], M1 = row_m[r1];
        float s0 = 0.f, s1 = 0.f;
        #pragma unroll
        for (int nf = 0; nf < 4; nf++) {
            const int jl = wn + nf*8 + 2*tig;
            float p0 = __expf(acc[nf][0] - M0);
            float p1 = __expf(acc[nf][1] - M0);
            float p2 = __expf(acc[nf][2] - M1);
            float p3 = __expf(acc[nf][3] - M1);
            s0 += p0 + p1;  s1 += p2 + p3;
            __nv_bfloat16 hh0,ll0,hh1,ll1;
            bsplit(p0,hh0,ll0); bsplit(p1,hh1,ll1);
            *(uint32_t*)&Ph[r0*ASP + jl] = pack2(hh0,hh1);
            *(uint32_t*)&Pl[r0*ASP + jl] = pack2(ll0,ll1);
            bsplit(p2,hh0,ll0); bsplit(p3,hh1,ll1);
            *(uint32_t*)&Ph[r1*ASP + jl] = pack2(hh0,hh1);
            *(uint32_t*)&Pl[r1*ASP + jl] = pack2(ll0,ll1);
        }
        s0 += __shfl_xor_sync(0xffffffffu, s0, 1);
        s0 += __shfl_xor_sync(0xffffffffu, s0, 2);
        s1 += __shfl_xor_sync(0xffffffffu, s1, 1);
        s1 += __shfl_xor_sync(0xffffffffu, s1, 2);
        if (tig == 0) { pm[wnh][r0] = s0; pm[wnh][r1] = s1; }
        __syncthreads();   // s4  (Ph/Pl + psums visible)
        if (tid < 64)
            row_l[tid] = row_l[tid]*alpha_s[tid] + pm[0][tid] + pm[1][tid];

        // ---- O rescale ----
        const float a0 = alpha_s[r0], a1 = alpha_s[r1];
        #pragma unroll
        for (int nf = 0; nf < 4; nf++) {
            o[nf][0] *= a0; o[nf][1] *= a0;
            o[nf][2] *= a1; o[nf][3] *= a1;
        }

        // ---- P @ V  (V via ldmatrix .trans: rows = j, 8 d-cols/frag) ----
        #pragma unroll
        for (int kk = 0; kk < 64; kk += 16) {
            uint32_t ph0,ph1,ph2,ph3, pl0,pl1,pl2,pl3;
            ldsm_x4(ph0,ph1,ph2,ph3, phB + kk*2);
            ldsm_x4(pl0,pl1,pl2,pl3, plB + kk*2);
            #pragma unroll
            for (int nf = 0; nf < 4; nf++) {
                const uint32_t voff = (uint32_t)(kk*ASP + nf*8)*2;
                uint32_t vh0,vh1, vl0,vl1;
                ldsm_x2t(vh0,vh1, vhB + voff);
                ldsm_x2t(vl0,vl1, vlB + voff);
                mma_bf16(o[nf], ph0,ph1,ph2,ph3, vh0,vh1);
                mma_bf16(o[nf], ph0,ph1,ph2,ph3, vl0,vl1);
                mma_bf16(o[nf], pl0,pl1,pl2,pl3, vh0,vh1);
            }
        }
    }
    __syncthreads();

    // ---- normalize, store ctx [b][s][h*64+d] ----
    const float inv0 = 1.f / row_l[r0];
    const float inv1 = 1.f / row_l[r1];
    #pragma unroll
    for (int nf = 0; nf < 4; nf++) {
        const int d = wn + nf*8 + 2*tig;
        float2 v0 = make_float2(o[nf][0]*inv0, o[nf][1]*inv0);
        float2 v1 = make_float2(o[nf][2]*inv1, o[nf][3]*inv1);
        *(float2*)(g_ctx + ((size_t)b*KS + i0 + r0)*KE + h*KD + d) = v0;
        *(float2*)(g_ctx + ((size_t)b*KS + i0 + r1)*KE + h*KD + d) = v1;
    }
}

// ---------------------------------------------------------------------------
// K6: output projection: out = ctx @ Wo^T + bo
// ---------------------------------------------------------------------------
__global__ void __launch_bounds__(256, 2)
out_kernel(const float* __restrict__ Wo, const float* __restrict__ bo,
           float* __restrict__ out)
{
    GEMM_SMEM
    const int m0 = blockIdx.y * 128;
    const int n0 = blockIdx.x * 128;

    float acc[4][4][4] = {};
    mma128_core(g_ctx, KE, m0, KB*KS, Wo, KE, n0, KIN, KE, acc, Ah, Al, Bh, Bl);

    const int lane = threadIdx.x & 31, warp = threadIdx.x >> 5;
    const int wm = (warp >> 2) * 64, wn = (warp & 3) * 32;
    const int g = lane >> 2, tig = lane & 3;
    #pragma unroll
    for (int mf = 0; mf < 4; mf++)
        #pragma unroll
        for (int nf = 0; nf < 4; nf++) {
            const int n = n0 + wn + nf*8 + 2*tig;
            const float2 bv2 = make_float2(bo[n], bo[n+1]);
            #pragma unroll
            for (int half = 0; half < 2; half++) {
                const int m = m0 + wm + mf*16 + g + half*8;
                float2 v;
                v.x = acc[mf][nf][half*2+0] + bv2.x;
                v.y = acc[mf][nf][half*2+1] + bv2.y;
                *(float2*)(out + (size_t)m*KIN + n) = v;
            }
        }
}

// ---------------------------------------------------------------------------
extern "C" void kernel_launch(void* const* d_in, const int* in_sizes, int n_in,
                              void* d_out, int out_size)
{
    const float* x    = (const float*)d_in[0];
    const int*   mask = (const int*)  d_in[1];
    const float* Wq   = (const float*)d_in[2];
    const float* bq   = (const float*)d_in[3];
    const float* Wk   = (const float*)d_in[4];
    const float* bk   = (const float*)d_in[5];
    const float* Wv   = (const float*)d_in[6];
    const float* bv   = (const float*)d_in[7];
    const float* rel  = (const float*)d_in[8];
    const float* Wpk  = (const float*)d_in[9];
    const float* bpk  = (const float*)d_in[10];
    const float* Wpq  = (const float*)d_in[11];
    const float* bpq  = (const float*)d_in[12];
    const float* Wo   = (const float*)d_in[13];
    const float* bo   = (const float*)d_in[14];

    dim3 thr(256);
    qkv_kernel   <<<dim3(1536/128, (KB*KS)/128), thr>>>(x, Wq, bq, Wk, bk, Wv, bv);
    pos_kernel   <<<dim3(1024/128, (KT + 127)/128), thr>>>(rel, Wpk, bpk, Wpq, bpq);
    disent_kernel<<<dim3((KT + 127)/128, KS/128, 2*KB*KH), thr>>>();
    attn_kernel  <<<dim3(KS/64, KH, KB), thr>>>(mask);
    out_kernel   <<<dim3(KIN/128, (KB*KS)/128), thr>>>(Wo, bo, (float*)d_out);
}

// round 14
// speedup vs baseline: 1.2883x; 1.0041x over previous
#include <cuda_runtime.h>
#include <cuda_bf16.h>
#include <cstdint>

// ---------------------------------------------------------------------------
// DeBERTa-style disentangled attention.
// B=8 S=384 IN=512 E=512 H=8 D=64, rel offsets t in [0,767), table row t+128.
// R14: attention rebuilt FA2-style: 128 threads / 4 warps, each warp = one
//      m16 row-frag x all 64 cols. Softmax fully in-warp (shfl), row state in
//      registers, P packed to A-frags in registers (no smem roundtrip),
//      Q frags loaded once. 2 syncs/j-tile. GEMM kernels unchanged from R12.
// ---------------------------------------------------------------------------

#define KB 8
#define KS 384
#define KIN 512
#define KE 512
#define KH 8
#define KD 64
#define KT 767            // 2*S-1 (logical)
#define KTP 768           // padded row stride for c2p/p2c scratch
#define KRELOFF 128       // table row = t + 128
#define KSCALE 0.07216878364870323f   // 1/sqrt(64*3)

#define BKP 40            // bf16 smem row stride (elems) = 80B -> conflict-free
#define TSZ (128*BKP)     // one tile buffer (elems)
#define ASP 72            // attn bf16 smem row stride (elems) = 144B -> conflict-free

__device__ float g_q[KB*KH*KS*KD];
__device__ float g_k[KB*KH*KS*KD];
__device__ float g_v[KB*KH*KS*KD];
__device__ float g_pk[KH*KT*KD];
__device__ float g_pq[KH*KT*KD];
__device__ float g_c2p[(size_t)KB*KH*KS*KTP];
__device__ float g_p2c[(size_t)KB*KH*KS*KTP];
__device__ float g_ctx[KB*KS*KE];

// ---------------------------------------------------------------------------
// bf16 / mma helpers
// ---------------------------------------------------------------------------
__device__ __forceinline__ void bsplit(float x, __nv_bfloat16& h, __nv_bfloat16& l)
{
    h = __float2bfloat16_rn(x);
    l = __float2bfloat16_rn(x - __bfloat162float(h));
}

__device__ __forceinline__ uint32_t pack2(__nv_bfloat16 a, __nv_bfloat16 b)
{
    __nv_bfloat162 t(a, b);
    return *reinterpret_cast<uint32_t*>(&t);
}

__device__ __forceinline__ void mma_bf16(float* d,
    uint32_t a0, uint32_t a1, uint32_t a2, uint32_t a3,
    uint32_t b0, uint32_t b1)
{
    asm("mma.sync.aligned.m16n8k16.row.col.f32.bf16.bf16.f32 "
        "{%0,%1,%2,%3}, {%4,%5,%6,%7}, {%8,%9}, {%0,%1,%2,%3};"
        : "+f"(d[0]), "+f"(d[1]), "+f"(d[2]), "+f"(d[3])
        : "r"(a0), "r"(a1), "r"(a2), "r"(a3), "r"(b0), "r"(b1));
}

__device__ __forceinline__ void ldsm_x4(uint32_t& r0, uint32_t& r1,
                                        uint32_t& r2, uint32_t& r3, uint32_t addr)
{
    asm volatile("ldmatrix.sync.aligned.m8n8.x4.shared.b16 {%0,%1,%2,%3}, [%4];"
        : "=r"(r0), "=r"(r1), "=r"(r2), "=r"(r3) : "r"(addr));
}

__device__ __forceinline__ void ldsm_x2(uint32_t& r0, uint32_t& r1, uint32_t addr)
{
    asm volatile("ldmatrix.sync.aligned.m8n8.x2.shared.b16 {%0,%1}, [%2];"
        : "=r"(r0), "=r"(r1) : "r"(addr));
}

__device__ __forceinline__ void ldsm_x2t(uint32_t& r0, uint32_t& r1, uint32_t addr)
{
    asm volatile("ldmatrix.sync.aligned.m8n8.x2.trans.shared.b16 {%0,%1}, [%2];"
        : "=r"(r0), "=r"(r1) : "r"(addr));
}

__device__ __forceinline__ void split4(float4 v, __nv_bfloat16* H, __nv_bfloat16* L, int off)
{
    __nv_bfloat16 hx,hy,hz,hw, lx,ly,lz,lw;
    bsplit(v.x,hx,lx); bsplit(v.y,hy,ly);
    bsplit(v.z,hz,lz); bsplit(v.w,hw,lw);
    *(uint2*)&H[off] = make_uint2(pack2(hx,hy), pack2(hz,hw));
    *(uint2*)&L[off] = make_uint2(pack2(lx,ly), pack2(lz,lw));
}

// ---------------------------------------------------------------------------
// 128x128 tile GEMM core (unchanged from R12 — verified).
// ---------------------------------------------------------------------------
__device__ __forceinline__ void mma128_core(
    const float* __restrict__ A, int lda, int a0r, int Mlim,
    const float* __restrict__ Bm, int ldb, int b0r, int Nlim,
    int K, float acc[4][4][4],
    __nv_bfloat16* Ah, __nv_bfloat16* Al,
    __nv_bfloat16* Bh, __nv_bfloat16* Bl)
{
    const int tid = threadIdx.x;
    const int lane = tid & 31, warp = tid >> 5;
    const int wm = (warp >> 2) * 64;
    const int wn = (warp & 3) * 32;
    const int lrow = tid >> 3;         // 0..31
    const int lk = (tid & 7) * 4;      // 0..28

    const int rA = lane & 15, kA = (lane >> 4) * 8;
    const int rB = lane & 7,  kB = ((lane >> 3) & 1) * 8;
    const uint32_t aHb = (uint32_t)__cvta_generic_to_shared(Ah) + ((wm + rA)*BKP + kA)*2;
    const uint32_t aLb = (uint32_t)__cvta_generic_to_shared(Al) + ((wm + rA)*BKP + kA)*2;
    const uint32_t bHb = (uint32_t)__cvta_generic_to_shared(Bh) + ((wn + rB)*BKP + kB)*2;
    const uint32_t bLb = (uint32_t)__cvta_generic_to_shared(Bl) + ((wn + rB)*BKP + kB)*2;

    for (int k0 = 0; k0 < K; k0 += 32) {
        __syncthreads();
        #pragma unroll
        for (int h4 = 0; h4 < 4; h4++) {
            const int row = lrow + h4 * 32;
            {
                const int ar = a0r + row;
                float4 v = make_float4(0.f, 0.f, 0.f, 0.f);
                if (ar < Mlim)
                    v = *(const float4*)(A + (size_t)ar * lda + k0 + lk);
                split4(v, Ah, Al, row*BKP + lk);
            }
            {
                const int br = b0r + row;
                float4 v = make_float4(0.f, 0.f, 0.f, 0.f);
                if (br < Nlim)
                    v = *(const float4*)(Bm + (size_t)br * ldb + k0 + lk);
                split4(v, Bh, Bl, row*BKP + lk);
            }
        }
        __syncthreads();
        #pragma unroll
        for (int kk = 0; kk < 32; kk += 16) {
            uint32_t bh_[4][2], bl_[4][2];
            #pragma unroll
            for (int nf = 0; nf < 4; nf++) {
                const uint32_t boff = (uint32_t)(nf*8*BKP + kk) * 2;
                ldsm_x2(bh_[nf][0], bh_[nf][1], bHb + boff);
                ldsm_x2(bl_[nf][0], bl_[nf][1], bLb + boff);
            }
            #pragma unroll
            for (int mf = 0; mf < 4; mf++) {
                const uint32_t aoff = (uint32_t)(mf*16*BKP + kk) * 2;
                uint32_t ah0,ah1,ah2,ah3, al0,al1,al2,al3;
                ldsm_x4(ah0,ah1,ah2,ah3, aHb + aoff);
                ldsm_x4(al0,al1,al2,al3, aLb + aoff);
                #pragma unroll
                for (int nf = 0; nf < 4; nf++) {
                    mma_bf16(acc[mf][nf], ah0,ah1,ah2,ah3, bh_[nf][0], bh_[nf][1]);
                    mma_bf16(acc[mf][nf], ah0,ah1,ah2,ah3, bl_[nf][0], bl_[nf][1]);
                    mma_bf16(acc[mf][nf], al0,al1,al2,al3, bh_[nf][0], bh_[nf][1]);
                }
            }
        }
    }
}

#define GEMM_SMEM \
    __shared__ __nv_bfloat16 Ah[TSZ], Al[TSZ], Bh[TSZ], Bl[TSZ];

// ---------------------------------------------------------------------------
// K1: fused QKV projection.
// ---------------------------------------------------------------------------
__global__ void __launch_bounds__(256, 2)
qkv_kernel(const float* __restrict__ x,
           const float* __restrict__ Wq, const float* __restrict__ bq,
           const float* __restrict__ Wk, const float* __restrict__ bk,
           const float* __restrict__ Wv, const float* __restrict__ bv)
{
    GEMM_SMEM
    const int m0 = blockIdx.y * 128;
    const int n0 = blockIdx.x * 128;
    const int which = n0 >> 9;
    const float* W    = (which == 0) ? Wq : (which == 1) ? Wk : Wv;
    const float* bias = (which == 0) ? bq : (which == 1) ? bk : bv;
    float* dst        = (which == 0) ? g_q : (which == 1) ? g_k : g_v;
    const int e0 = n0 & 511;

    float acc[4][4][4] = {};
    mma128_core(x, KIN, m0, KB*KS, W, KIN, e0, KE, KIN, acc, Ah, Al, Bh, Bl);

    const int lane = threadIdx.x & 31, warp = threadIdx.x >> 5;
    const int wm = (warp >> 2) * 64, wn = (warp & 3) * 32;
    const int g = lane >> 2, tig = lane & 3;
    #pragma unroll
    for (int mf = 0; mf < 4; mf++)
        #pragma unroll
        for (int nf = 0; nf < 4; nf++) {
            const int e = e0 + wn + nf*8 + 2*tig;       // even
            const int h = e >> 6, d0 = e & 63;
            const float2 bv2 = make_float2(bias[e], bias[e+1]);
            #pragma unroll
            for (int half = 0; half < 2; half++) {
                const int m = m0 + wm + mf*16 + g + half*8;
                const int b = m / KS, s = m % KS;
                float2 v;
                v.x = acc[mf][nf][half*2+0] + bv2.x;
                v.y = acc[mf][nf][half*2+1] + bv2.y;
                *(float2*)(dst + ((size_t)(b*KH + h)*KS + s)*KD + d0) = v;
            }
        }
}

// ---------------------------------------------------------------------------
// K2: positional projections PK[t] / PQ[t].
// ---------------------------------------------------------------------------
__global__ void __launch_bounds__(256, 2)
pos_kernel(const float* __restrict__ rel_table,
           const float* __restrict__ Wpk, const float* __restrict__ bpk,
           const float* __restrict__ Wpq, const float* __restrict__ bpq)
{
    GEMM_SMEM
    const int m0 = blockIdx.y * 128;
    const int n0 = blockIdx.x * 128;
    const bool isq = (n0 >= 512);
    const float* W    = isq ? Wpq : Wpk;
    const float* bias = isq ? bpq : bpk;
    float* dst        = isq ? g_pq : g_pk;
    const int e0 = n0 & 511;

    float acc[4][4][4] = {};
    mma128_core(rel_table + (size_t)KRELOFF*KIN, KIN, m0, KT,
                W, KIN, e0, KE, KIN, acc, Ah, Al, Bh, Bl);

    const int lane = threadIdx.x & 31, warp = threadIdx.x >> 5;
    const int wm = (warp >> 2) * 64, wn = (warp & 3) * 32;
    const int g = lane >> 2, tig = lane & 3;
    #pragma unroll
    for (int mf = 0; mf < 4; mf++)
        #pragma unroll
        for (int nf = 0; nf < 4; nf++) {
            const int e = e0 + wn + nf*8 + 2*tig;
            const int h = e >> 6, d0 = e & 63;
            const float2 bv2 = make_float2(bias[e], bias[e+1]);
            #pragma unroll
            for (int half = 0; half < 2; half++) {
                const int t = m0 + wm + mf*16 + g + half*8;
                if (t >= KT) continue;
                float2 v;
                v.x = acc[mf][nf][half*2+0] + bv2.x;
                v.y = acc[mf][nf][half*2+1] + bv2.y;
                *(float2*)(dst + ((size_t)h*KT + t)*KD + d0) = v;
            }
        }
}

// ---------------------------------------------------------------------------
// K3: disentangled score tables, both passes in one launch (which = z>>6).
// ---------------------------------------------------------------------------
__global__ void __launch_bounds__(256, 2)
disent_kernel()
{
    const int which = blockIdx.z >> 6;
    const int bh = blockIdx.z & 63;
    const int i0 = blockIdx.y * 128;
    const int t0 = blockIdx.x * 128;
    const int r_max = (i0 + 127 < KS - 1) ? i0 + 127 : KS - 1;
    int t_lo, t_hi;
    if (which == 0) { t_lo = (KS - 1) - r_max;  t_hi = (2*KS - 2) - i0; }
    else            { t_lo = i0;                t_hi = r_max + (KS - 1); }
    if (t0 > t_hi || t0 + 127 < t_lo) return;

    GEMM_SMEM
    const int h  = bh & 7;
    const float* vecs = which ? g_k  : g_q;
    const float* pos  = which ? g_pq : g_pk;
    float*       out  = which ? g_p2c : g_c2p;

    float acc[4][4][4] = {};
    mma128_core(vecs + (size_t)bh*KS*KD, KD, i0, KS,
                pos  + (size_t)h*KT*KD,  KD, t0, KT, KD, acc, Ah, Al, Bh, Bl);

    const int lane = threadIdx.x & 31, warp = threadIdx.x >> 5;
    const int wm = (warp >> 2) * 64, wn = (warp & 3) * 32;
    const int g = lane >> 2, tig = lane & 3;
    #pragma unroll
    for (int mf = 0; mf < 4; mf++)
        #pragma unroll
        for (int half = 0; half < 2; half++) {
            const int i = i0 + wm + mf*16 + g + half*8;
            float* orow = out + ((size_t)bh*KS + i)*KTP;
            #pragma unroll
            for (int nf = 0; nf < 4; nf++) {
                const int t = t0 + wn + nf*8 + 2*tig;
                float2 v;
                v.x = acc[mf][nf][half*2+0];
                v.y = acc[mf][nf][half*2+1];
                *(float2*)(orow + t) = v;
            }
        }
}

// ---------------------------------------------------------------------------
// K5: flash attention, register-resident FA2 style.
// 128 threads / 4 warps; warp w owns rows [w*16, w*16+16) x ALL 64 cols
// (8 n8 fragments). Softmax in-warp (shfl over tig); m/l/alpha in registers;
// P packed to A-fragments in registers (S-frag layout == A-frag layout);
// Q fragments loaded once. 2 syncthreads per j-tile.
// ---------------------------------------------------------------------------
__global__ void __launch_bounds__(128, 3)
attn_kernel(const int* __restrict__ mask)
{
    __shared__ __nv_bfloat16 KhS[64*ASP], KlS[64*ASP];
    __shared__ __nv_bfloat16 VhS[64*ASP], VlS[64*ASP];
    __shared__ float band[64*68];
    __shared__ int   msks[64];

    const int i0 = blockIdx.x * 64;
    const int h  = blockIdx.y;
    const int b  = blockIdx.z;
    const int bh = b*KH + h;
    const float* qb   = g_q + (size_t)bh*KS*KD;
    const float* kb   = g_k + (size_t)bh*KS*KD;
    const float* vb   = g_v + (size_t)bh*KS*KD;
    const float* c2pb = g_c2p + (size_t)bh*KS*KTP;
    const float* p2cb = g_p2c + (size_t)bh*KS*KTP;

    const int tid = threadIdx.x;
    const int lane = tid & 31, warp = tid >> 5;
    const int wm = warp * 16;
    const int g = lane >> 2, tig = lane & 3;
    const int r0 = wm + g, r1 = r0 + 8;

    // ldmatrix lane bases
    const int rA = lane & 15, kA = (lane >> 4) * 8;    // A x4 (rows = m)
    const int rB = lane & 7,  kBo = ((lane >> 3) & 1) * 8;  // B x2 non-trans
    const int rV = lane & 15;                           // B x2 trans (rows = k)

    const uint32_t khB = (uint32_t)__cvta_generic_to_shared(KhS) + (rB*ASP + kBo)*2;
    const uint32_t klB = (uint32_t)__cvta_generic_to_shared(KlS) + (rB*ASP + kBo)*2;
    const uint32_t vhB = (uint32_t)__cvta_generic_to_shared(VhS) + (rV*ASP)*2;
    const uint32_t vlB = (uint32_t)__cvta_generic_to_shared(VlS) + (rV*ASP)*2;
    const uint32_t qhB = (uint32_t)__cvta_generic_to_shared(KhS) + ((wm + rA)*ASP + kA)*2;
    const uint32_t qlB = (uint32_t)__cvta_generic_to_shared(KlS) + ((wm + rA)*ASP + kA)*2;

    // ---- stage Q through K buffers, load Q fragments once ----
    {
        const int row = tid >> 1, kb4 = (tid & 1) * 32;
        const float* src = qb + (size_t)(i0 + row)*KD + kb4;
        #pragma unroll
        for (int qq = 0; qq < 8; qq++)
            split4(*(const float4*)(src + qq*4), KhS, KlS, row*ASP + kb4 + qq*4);
    }
    __syncthreads();
    uint32_t qh[4][4], ql[4][4];
    #pragma unroll
    for (int t = 0; t < 4; t++) {
        ldsm_x4(qh[t][0], qh[t][1], qh[t][2], qh[t][3], qhB + t*32);  // 16 elems * 2B
        ldsm_x4(ql[t][0], ql[t][1], ql[t][2], ql[t][3], qlB + t*32);
    }

    float m0 = -1e30f, m1 = -1e30f, l0 = 0.f, l1 = 0.f;
    float o[8][4] = {};

    for (int j0 = 0; j0 < KS; j0 += 64) {
        __syncthreads();   // Q frags read (iter 0) / prev-tile reads complete

        // ---- stage K, V (split hi/lo) ----
        {
            const int row = tid >> 1, kb4 = (tid & 1) * 32;
            const float* ks = kb + (size_t)(j0 + row)*KD + kb4;
            const float* vs = vb + (size_t)(j0 + row)*KD + kb4;
            #pragma unroll
            for (int qq = 0; qq < 8; qq++) {
                split4(*(const float4*)(ks + qq*4), KhS, KlS, row*ASP + kb4 + qq*4);
                split4(*(const float4*)(vs + qq*4), VhS, VlS, row*ASP + kb4 + qq*4);
            }
        }
        // ---- stage p2c band: band[jl][x]; value for row r is band[jl][63-r] ----
        {
            const int c = tid >> 1, q2 = tid & 1;
            const float* src = p2cb + (size_t)(j0 + c)*KTP + (j0 + c - i0 + 320);
            #pragma unroll
            for (int xx = 0; xx < 32; xx++) {
                const int x = q2 + xx*2;
                band[c*68 + x] = src[x];
            }
        }
        if (tid < 64) msks[tid] = mask[b*KS + j0 + tid];
        __syncthreads();

        // ---- c2c: Q @ K^T  (8 n-frags, Q frags in regs) ----
        float sacc[8][4] = {};
        #pragma unroll
        for (int t = 0; t < 4; t++) {
            #pragma unroll
            for (int nf = 0; nf < 8; nf++) {
                const uint32_t boff = (uint32_t)(nf*8*ASP + t*16)*2;
                uint32_t b0h,b1h, b0l,b1l;
                ldsm_x2(b0h,b1h, khB + boff);
                ldsm_x2(b0l,b1l, klB + boff);
                mma_bf16(sacc[nf], qh[t][0],qh[t][1],qh[t][2],qh[t][3], b0h,b1h);
                mma_bf16(sacc[nf], qh[t][0],qh[t][1],qh[t][2],qh[t][3], b0l,b1l);
                mma_bf16(sacc[nf], ql[t][0],ql[t][1],ql[t][2],ql[t][3], b0h,b1h);
            }
        }

        // ---- logits = (c2c + c2p + p2c)*SCALE, mask; in-warp row max ----
        const float* c0row = c2pb + (size_t)(i0 + r0)*KTP + (j0 - (i0 + r0) + 383);
        const float* c1row = c2pb + (size_t)(i0 + r1)*KTP + (j0 - (i0 + r1) + 383);
        float nm0 = m0, nm1 = m1;
        #pragma unroll
        for (int nf = 0; nf < 8; nf++) {
            const int jl = nf*8 + 2*tig;
            float v0 = (sacc[nf][0] + c0row[jl]   + band[jl*68     + 63 - r0]) * KSCALE;
            float v1 = (sacc[nf][1] + c0row[jl+1] + band[(jl+1)*68 + 63 - r0]) * KSCALE;
            float v2 = (sacc[nf][2] + c1row[jl]   + band[jl*68     + 63 - r1]) * KSCALE;
            float v3 = (sacc[nf][3] + c1row[jl+1] + band[(jl+1)*68 + 63 - r1]) * KSCALE;
            if (msks[jl]   == 0) { v0 = -9e15f; v2 = -9e15f; }
            if (msks[jl+1] == 0) { v1 = -9e15f; v3 = -9e15f; }
            sacc[nf][0] = v0; sacc[nf][1] = v1; sacc[nf][2] = v2; sacc[nf][3] = v3;
            nm0 = fmaxf(nm0, fmaxf(v0, v1));
            nm1 = fmaxf(nm1, fmaxf(v2, v3));
        }
        nm0 = fmaxf(nm0, __shfl_xor_sync(0xffffffffu, nm0, 1));
        nm0 = fmaxf(nm0, __shfl_xor_sync(0xffffffffu, nm0, 2));
        nm1 = fmaxf(nm1, __shfl_xor_sync(0xffffffffu, nm1, 1));
        nm1 = fmaxf(nm1, __shfl_xor_sync(0xffffffffu, nm1, 2));
        const float alpha0 = __expf(m0 - nm0);
        const float alpha1 = __expf(m1 - nm1);
        m0 = nm0; m1 = nm1;

        // ---- p = exp(l - m); in-warp row sums ----
        float s0 = 0.f, s1 = 0.f;
        #pragma unroll
        for (int nf = 0; nf < 8; nf++) {
            float p0 = __expf(sacc[nf][0] - m0);
            float p1 = __expf(sacc[nf][1] - m0);
            float p2 = __expf(sacc[nf][2] - m1);
            float p3 = __expf(sacc[nf][3] - m1);
            sacc[nf][0] = p0; sacc[nf][1] = p1; sacc[nf][2] = p2; sacc[nf][3] = p3;
            s0 += p0 + p1;  s1 += p2 + p3;
        }
        s0 += __shfl_xor_sync(0xffffffffu, s0, 1);
        s0 += __shfl_xor_sync(0xffffffffu, s0, 2);
        s1 += __shfl_xor_sync(0xffffffffu, s1, 1);
        s1 += __shfl_xor_sync(0xffffffffu, s1, 2);
        l0 = l0*alpha0 + s0;
        l1 = l1*alpha1 + s1;

        // ---- O rescale ----
        #pragma unroll
        for (int nf = 0; nf < 8; nf++) {
            o[nf][0] *= alpha0; o[nf][1] *= alpha0;
            o[nf][2] *= alpha1; o[nf][3] *= alpha1;
        }

        // ---- P @ V: pack A-frags from sacc in registers; V via .trans ----
        #pragma unroll
        for (int t = 0; t < 4; t++) {
            uint32_t pah[4], pal[4];
            {
                __nv_bfloat16 ha,la, hb,lb;
                bsplit(sacc[2*t][0], ha, la);  bsplit(sacc[2*t][1], hb, lb);
                pah[0] = pack2(ha,hb);  pal[0] = pack2(la,lb);
                bsplit(sacc[2*t][2], ha, la);  bsplit(sacc[2*t][3], hb, lb);
                pah[1] = pack2(ha,hb);  pal[1] = pack2(la,lb);
                bsplit(sacc[2*t+1][0], ha, la); bsplit(sacc[2*t+1][1], hb, lb);
                pah[2] = pack2(ha,hb);  pal[2] = pack2(la,lb);
                bsplit(sacc[2*t+1][2], ha, la); bsplit(sacc[2*t+1][3], hb, lb);
                pah[3] = pack2(ha,hb);  pal[3] = pack2(la,lb);
            }
            #pragma unroll
            for (int nf = 0; nf < 8; nf++) {
                const uint32_t voff = (uint32_t)(t*16*ASP + nf*8)*2;
                uint32_t vh0,vh1, vl0,vl1;
                ldsm_x2t(vh0,vh1, vhB + voff);
                ldsm_x2t(vl0,vl1, vlB + voff);
                mma_bf16(o[nf], pah[0],pah[1],pah[2],pah[3], vh0,vh1);
                mma_bf16(o[nf], pah[0],pah[1],pah[2],pah[3], vl0,vl1);
                mma_bf16(o[nf], pal[0],pal[1],pal[2],pal[3], vh0,vh1);
            }
        }
    }

    // ---- normalize, store ctx [b][s][h*64+d] ----
    const float inv0 = 1.f / l0;
    const float inv1 = 1.f / l1;
    #pragma unroll
    for (int nf = 0; nf < 8; nf++) {
        const int d = nf*8 + 2*tig;
        float2 v0 = make_float2(o[nf][0]*inv0, o[nf][1]*inv0);
        float2 v1 = make_float2(o[nf][2]*inv1, o[nf][3]*inv1);
        *(float2*)(g_ctx + ((size_t)b*KS + i0 + r0)*KE + h*KD + d) = v0;
        *(float2*)(g_ctx + ((size_t)b*KS + i0 + r1)*KE + h*KD + d) = v1;
    }
}

// ---------------------------------------------------------------------------
// K6: output projection: out = ctx @ Wo^T + bo
// ---------------------------------------------------------------------------
__global__ void __launch_bounds__(256, 2)
out_kernel(const float* __restrict__ Wo, const float* __restrict__ bo,
           float* __restrict__ out)
{
    GEMM_SMEM
    const int m0 = blockIdx.y * 128;
    const int n0 = blockIdx.x * 128;

    float acc[4][4][4] = {};
    mma128_core(g_ctx, KE, m0, KB*KS, Wo, KE, n0, KIN, KE, acc, Ah, Al, Bh, Bl);

    const int lane = threadIdx.x & 31, warp = threadIdx.x >> 5;
    const int wm = (warp >> 2) * 64, wn = (warp & 3) * 32;
    const int g = lane >> 2, tig = lane & 3;
    #pragma unroll
    for (int mf = 0; mf < 4; mf++)
        #pragma unroll
        for (int nf = 0; nf < 4; nf++) {
            const int n = n0 + wn + nf*8 + 2*tig;
            const float2 bv2 = make_float2(bo[n], bo[n+1]);
            #pragma unroll
            for (int half = 0; half < 2; half++) {
                const int m = m0 + wm + mf*16 + g + half*8;
                float2 v;
                v.x = acc[mf][nf][half*2+0] + bv2.x;
                v.y = acc[mf][nf][half*2+1] + bv2.y;
                *(float2*)(out + (size_t)m*KIN + n) = v;
            }
        }
}

// ---------------------------------------------------------------------------
extern "C" void kernel_launch(void* const* d_in, const int* in_sizes, int n_in,
                              void* d_out, int out_size)
{
    const float* x    = (const float*)d_in[0];
    const int*   mask = (const int*)  d_in[1];
    const float* Wq   = (const float*)d_in[2];
    const float* bq   = (const float*)d_in[3];
    const float* Wk   = (const float*)d_in[4];
    const float* bk   = (const float*)d_in[5];
    const float* Wv   = (const float*)d_in[6];
    const float* bv   = (const float*)d_in[7];
    const float* rel  = (const float*)d_in[8];
    const float* Wpk  = (const float*)d_in[9];
    const float* bpk  = (const float*)d_in[10];
    const float* Wpq  = (const float*)d_in[11];
    const float* bpq  = (const float*)d_in[12];
    const float* Wo   = (const float*)d_in[13];
    const float* bo   = (const float*)d_in[14];

    dim3 thr(256);
    qkv_kernel   <<<dim3(1536/128, (KB*KS)/128), thr>>>(x, Wq, bq, Wk, bk, Wv, bv);
    pos_kernel   <<<dim3(1024/128, (KT + 127)/128), thr>>>(rel, Wpk, bpk, Wpq, bpq);
    disent_kernel<<<dim3((KT + 127)/128, KS/128, 2*KB*KH), thr>>>();
    attn_kernel  <<<dim3(KS/64, KH, KB), dim3(128)>>>(mask);
    out_kernel   <<<dim3(KIN/128, (KB*KS)/128), thr>>>(Wo, bo, (float*)d_out);
}

// round 15
// speedup vs baseline: 1.2964x; 1.0063x over previous
#include <cuda_runtime.h>
#include <cuda_bf16.h>
#include <cstdint>

// ---------------------------------------------------------------------------
// DeBERTa-style disentangled attention.
// B=8 S=384 IN=512 E=512 H=8 D=64, rel offsets t in [0,767), table row t+128.
// R15: (1) c2p table diagonalized: c2pd[bh][i][j] (384 wide) written by the
//      disent c2p pass (j = t+i-383, bounds-checked) -> attn reads aligned
//      coalesced float2, traffic halved. (2) x4 ldmatrix for paired n-frags
//      in attn (K non-trans, V trans) and GEMM-core B side. p2c unchanged.
// ---------------------------------------------------------------------------

#define KB 8
#define KS 384
#define KIN 512
#define KE 512
#define KH 8
#define KD 64
#define KT 767            // 2*S-1 (logical)
#define KTP 768           // padded row stride for p2c scratch
#define KRELOFF 128       // table row = t + 128
#define KSCALE 0.07216878364870323f   // 1/sqrt(64*3)

#define BKP 40            // bf16 smem row stride (elems) = 80B -> conflict-free
#define TSZ (128*BKP)     // one tile buffer (elems)
#define ASP 72            // attn bf16 smem row stride (elems) = 144B -> conflict-free

__device__ float g_q[KB*KH*KS*KD];
__device__ float g_k[KB*KH*KS*KD];
__device__ float g_v[KB*KH*KS*KD];
__device__ float g_pk[KH*KT*KD];
__device__ float g_pq[KH*KT*KD];
__device__ float g_c2p[(size_t)KB*KH*KS*KS];   // diagonalized [bh][i][j]
__device__ float g_p2c[(size_t)KB*KH*KS*KTP];  // [bh][j][t]
__device__ float g_ctx[KB*KS*KE];

// ---------------------------------------------------------------------------
// bf16 / mma helpers
// ---------------------------------------------------------------------------
__device__ __forceinline__ void bsplit(float x, __nv_bfloat16& h, __nv_bfloat16& l)
{
    h = __float2bfloat16_rn(x);
    l = __float2bfloat16_rn(x - __bfloat162float(h));
}

__device__ __forceinline__ uint32_t pack2(__nv_bfloat16 a, __nv_bfloat16 b)
{
    __nv_bfloat162 t(a, b);
    return *reinterpret_cast<uint32_t*>(&t);
}

__device__ __forceinline__ void mma_bf16(float* d,
    uint32_t a0, uint32_t a1, uint32_t a2, uint32_t a3,
    uint32_t b0, uint32_t b1)
{
    asm("mma.sync.aligned.m16n8k16.row.col.f32.bf16.bf16.f32 "
        "{%0,%1,%2,%3}, {%4,%5,%6,%7}, {%8,%9}, {%0,%1,%2,%3};"
        : "+f"(d[0]), "+f"(d[1]), "+f"(d[2]), "+f"(d[3])
        : "r"(a0), "r"(a1), "r"(a2), "r"(a3), "r"(b0), "r"(b1));
}

__device__ __forceinline__ void ldsm_x4(uint32_t& r0, uint32_t& r1,
                                        uint32_t& r2, uint32_t& r3, uint32_t addr)
{
    asm volatile("ldmatrix.sync.aligned.m8n8.x4.shared.b16 {%0,%1,%2,%3}, [%4];"
        : "=r"(r0), "=r"(r1), "=r"(r2), "=r"(r3) : "r"(addr));
}

__device__ __forceinline__ void ldsm_x4t(uint32_t& r0, uint32_t& r1,
                                         uint32_t& r2, uint32_t& r3, uint32_t addr)
{
    asm volatile("ldmatrix.sync.aligned.m8n8.x4.trans.shared.b16 {%0,%1,%2,%3}, [%4];"
        : "=r"(r0), "=r"(r1), "=r"(r2), "=r"(r3) : "r"(addr));
}

__device__ __forceinline__ void split4(float4 v, __nv_bfloat16* H, __nv_bfloat16* L, int off)
{
    __nv_bfloat16 hx,hy,hz,hw, lx,ly,lz,lw;
    bsplit(v.x,hx,lx); bsplit(v.y,hy,ly);
    bsplit(v.z,hz,lz); bsplit(v.w,hw,lw);
    *(uint2*)&H[off] = make_uint2(pack2(hx,hy), pack2(hz,hw));
    *(uint2*)&L[off] = make_uint2(pack2(lx,ly), pack2(lz,lw));
}

// ---------------------------------------------------------------------------
// 128x128 tile GEMM core, 256 threads, BK=32, bf16 3-term mma.
// B fragments via x4 (2 n-frags per ldmatrix):
//   lanes 0-7: rows of nf=2p (k+0) | 8-15: nf=2p (k+8) |
//   16-23: nf=2p+1 (k+0) | 24-31: nf=2p+1 (k+8)  -> regs (b0,b1,b0',b1').
// ---------------------------------------------------------------------------
__device__ __forceinline__ void mma128_core(
    const float* __restrict__ A, int lda, int a0r, int Mlim,
    const float* __restrict__ Bm, int ldb, int b0r, int Nlim,
    int K, float acc[4][4][4],
    __nv_bfloat16* Ah, __nv_bfloat16* Al,
    __nv_bfloat16* Bh, __nv_bfloat16* Bl)
{
    const int tid = threadIdx.x;
    const int lane = tid & 31, warp = tid >> 5;
    const int wm = (warp >> 2) * 64;
    const int wn = (warp & 3) * 32;
    const int lrow = tid >> 3;         // 0..31
    const int lk = (tid & 7) * 4;      // 0..28

    const int rA = lane & 15, kA = (lane >> 4) * 8;
    const int rB4 = (lane & 7) + ((lane >> 4) & 1) * 8;
    const int kB4 = ((lane >> 3) & 1) * 8;
    const uint32_t aHb = (uint32_t)__cvta_generic_to_shared(Ah) + ((wm + rA)*BKP + kA)*2;
    const uint32_t aLb = (uint32_t)__cvta_generic_to_shared(Al) + ((wm + rA)*BKP + kA)*2;
    const uint32_t bHb = (uint32_t)__cvta_generic_to_shared(Bh) + ((wn + rB4)*BKP + kB4)*2;
    const uint32_t bLb = (uint32_t)__cvta_generic_to_shared(Bl) + ((wn + rB4)*BKP + kB4)*2;

    for (int k0 = 0; k0 < K; k0 += 32) {
        __syncthreads();
        #pragma unroll
        for (int h4 = 0; h4 < 4; h4++) {
            const int row = lrow + h4 * 32;
            {
                const int ar = a0r + row;
                float4 v = make_float4(0.f, 0.f, 0.f, 0.f);
                if (ar < Mlim)
                    v = *(const float4*)(A + (size_t)ar * lda + k0 + lk);
                split4(v, Ah, Al, row*BKP + lk);
            }
            {
                const int br = b0r + row;
                float4 v = make_float4(0.f, 0.f, 0.f, 0.f);
                if (br < Nlim)
                    v = *(const float4*)(Bm + (size_t)br * ldb + k0 + lk);
                split4(v, Bh, Bl, row*BKP + lk);
            }
        }
        __syncthreads();
        #pragma unroll
        for (int kk = 0; kk < 32; kk += 16) {
            uint32_t bh_[4][2], bl_[4][2];
            #pragma unroll
            for (int p = 0; p < 2; p++) {
                const uint32_t boff = (uint32_t)(p*16*BKP + kk) * 2;
                ldsm_x4(bh_[2*p][0], bh_[2*p][1], bh_[2*p+1][0], bh_[2*p+1][1], bHb + boff);
                ldsm_x4(bl_[2*p][0], bl_[2*p][1], bl_[2*p+1][0], bl_[2*p+1][1], bLb + boff);
            }
            #pragma unroll
            for (int mf = 0; mf < 4; mf++) {
                const uint32_t aoff = (uint32_t)(mf*16*BKP + kk) * 2;
                uint32_t ah0,ah1,ah2,ah3, al0,al1,al2,al3;
                ldsm_x4(ah0,ah1,ah2,ah3, aHb + aoff);
                ldsm_x4(al0,al1,al2,al3, aLb + aoff);
                #pragma unroll
                for (int nf = 0; nf < 4; nf++) {
                    mma_bf16(acc[mf][nf], ah0,ah1,ah2,ah3, bh_[nf][0], bh_[nf][1]);
                    mma_bf16(acc[mf][nf], ah0,ah1,ah2,ah3, bl_[nf][0], bl_[nf][1]);
                    mma_bf16(acc[mf][nf], al0,al1,al2,al3, bh_[nf][0], bh_[nf][1]);
                }
            }
        }
    }
}

#define GEMM_SMEM \
    __shared__ __nv_bfloat16 Ah[TSZ], Al[TSZ], Bh[TSZ], Bl[TSZ];

// ---------------------------------------------------------------------------
// K1: fused QKV projection.
// ---------------------------------------------------------------------------
__global__ void __launch_bounds__(256, 2)
qkv_kernel(const float* __restrict__ x,
           const float* __restrict__ Wq, const float* __restrict__ bq,
           const float* __restrict__ Wk, const float* __restrict__ bk,
           const float* __restrict__ Wv, const float* __restrict__ bv)
{
    GEMM_SMEM
    const int m0 = blockIdx.y * 128;
    const int n0 = blockIdx.x * 128;
    const int which = n0 >> 9;
    const float* W    = (which == 0) ? Wq : (which == 1) ? Wk : Wv;
    const float* bias = (which == 0) ? bq : (which == 1) ? bk : bv;
    float* dst        = (which == 0) ? g_q : (which == 1) ? g_k : g_v;
    const int e0 = n0 & 511;

    float acc[4][4][4] = {};
    mma128_core(x, KIN, m0, KB*KS, W, KIN, e0, KE, KIN, acc, Ah, Al, Bh, Bl);

    const int lane = threadIdx.x & 31, warp = threadIdx.x >> 5;
    const int wm = (warp >> 2) * 64, wn = (warp & 3) * 32;
    const int g = lane >> 2, tig = lane & 3;
    #pragma unroll
    for (int mf = 0; mf < 4; mf++)
        #pragma unroll
        for (int nf = 0; nf < 4; nf++) {
            const int e = e0 + wn + nf*8 + 2*tig;       // even
            const int h = e >> 6, d0 = e & 63;
            const float2 bv2 = make_float2(bias[e], bias[e+1]);
            #pragma unroll
            for (int half = 0; half < 2; half++) {
                const int m = m0 + wm + mf*16 + g + half*8;
                const int b = m / KS, s = m % KS;
                float2 v;
                v.x = acc[mf][nf][half*2+0] + bv2.x;
                v.y = acc[mf][nf][half*2+1] + bv2.y;
                *(float2*)(dst + ((size_t)(b*KH + h)*KS + s)*KD + d0) = v;
            }
        }
}

// ---------------------------------------------------------------------------
// K2: positional projections PK[t] / PQ[t].
// ---------------------------------------------------------------------------
__global__ void __launch_bounds__(256, 2)
pos_kernel(const float* __restrict__ rel_table,
           const float* __restrict__ Wpk, const float* __restrict__ bpk,
           const float* __restrict__ Wpq, const float* __restrict__ bpq)
{
    GEMM_SMEM
    const int m0 = blockIdx.y * 128;
    const int n0 = blockIdx.x * 128;
    const bool isq = (n0 >= 512);
    const float* W    = isq ? Wpq : Wpk;
    const float* bias = isq ? bpq : bpk;
    float* dst        = isq ? g_pq : g_pk;
    const int e0 = n0 & 511;

    float acc[4][4][4] = {};
    mma128_core(rel_table + (size_t)KRELOFF*KIN, KIN, m0, KT,
                W, KIN, e0, KE, KIN, acc, Ah, Al, Bh, Bl);

    const int lane = threadIdx.x & 31, warp = threadIdx.x >> 5;
    const int wm = (warp >> 2) * 64, wn = (warp & 3) * 32;
    const int g = lane >> 2, tig = lane & 3;
    #pragma unroll
    for (int mf = 0; mf < 4; mf++)
        #pragma unroll
        for (int nf = 0; nf < 4; nf++) {
            const int e = e0 + wn + nf*8 + 2*tig;
            const int h = e >> 6, d0 = e & 63;
            const float2 bv2 = make_float2(bias[e], bias[e+1]);
            #pragma unroll
            for (int half = 0; half < 2; half++) {
                const int t = m0 + wm + mf*16 + g + half*8;
                if (t >= KT) continue;
                float2 v;
                v.x = acc[mf][nf][half*2+0] + bv2.x;
                v.y = acc[mf][nf][half*2+1] + bv2.y;
                *(float2*)(dst + ((size_t)h*KT + t)*KD + d0) = v;
            }
        }
}

// ---------------------------------------------------------------------------
// K3: disentangled score tables, both passes in one launch (which = z>>6).
//   which==0: C2P: acc(i,t) stored DIAGONALIZED at c2pd[bh][i][j], j=t+i-383
//             (each valid j in [0,384) written exactly once). Window as before.
//   which==1: P2C[bh][j][t], window [i0, r_max+383], stride KTP.
// ---------------------------------------------------------------------------
__global__ void __launch_bounds__(256, 2)
disent_kernel()
{
    const int which = blockIdx.z >> 6;
    const int bh = blockIdx.z & 63;
    const int i0 = blockIdx.y * 128;
    const int t0 = blockIdx.x * 128;
    const int r_max = (i0 + 127 < KS - 1) ? i0 + 127 : KS - 1;
    int t_lo, t_hi;
    if (which == 0) { t_lo = (KS - 1) - r_max;  t_hi = (2*KS - 2) - i0; }
    else            { t_lo = i0;                t_hi = r_max + (KS - 1); }
    if (t0 > t_hi || t0 + 127 < t_lo) return;

    GEMM_SMEM
    const int h  = bh & 7;
    const float* vecs = which ? g_k  : g_q;
    const float* pos  = which ? g_pq : g_pk;

    float acc[4][4][4] = {};
    mma128_core(vecs + (size_t)bh*KS*KD, KD, i0, KS,
                pos  + (size_t)h*KT*KD,  KD, t0, KT, KD, acc, Ah, Al, Bh, Bl);

    const int lane = threadIdx.x & 31, warp = threadIdx.x >> 5;
    const int wm = (warp >> 2) * 64, wn = (warp & 3) * 32;
    const int g = lane >> 2, tig = lane & 3;

    if (which == 0) {
        // diagonalized store: row i, col j = t + i - 383, scalar w/ bounds
        #pragma unroll
        for (int mf = 0; mf < 4; mf++)
            #pragma unroll
            for (int half = 0; half < 2; half++) {
                const int i = i0 + wm + mf*16 + g + half*8;
                float* orow = g_c2p + ((size_t)bh*KS + i)*KS;
                const int jb = i - (KS - 1);
                #pragma unroll
                for (int nf = 0; nf < 4; nf++) {
                    const int t = t0 + wn + nf*8 + 2*tig;
                    const int j = t + jb;
                    if ((unsigned)j < KS)     orow[j]   = acc[mf][nf][half*2+0];
                    if ((unsigned)(j+1) < KS) orow[j+1] = acc[mf][nf][half*2+1];
                }
            }
    } else {
        #pragma unroll
        for (int mf = 0; mf < 4; mf++)
            #pragma unroll
            for (int half = 0; half < 2; half++) {
                const int i = i0 + wm + mf*16 + g + half*8;
                float* orow = g_p2c + ((size_t)bh*KS + i)*KTP;
                #pragma unroll
                for (int nf = 0; nf < 4; nf++) {
                    const int t = t0 + wn + nf*8 + 2*tig;
                    float2 v;
                    v.x = acc[mf][nf][half*2+0];
                    v.y = acc[mf][nf][half*2+1];
                    *(float2*)(orow + t) = v;
                }
            }
    }
}

// ---------------------------------------------------------------------------
// K5: flash attention, register-resident, x4 ldmatrix.
// 128 threads / 4 warps; warp w owns rows [w*16, w*16+16) x all 64 cols.
// ---------------------------------------------------------------------------
__global__ void __launch_bounds__(128, 3)
attn_kernel(const int* __restrict__ mask)
{
    __shared__ __nv_bfloat16 KhS[64*ASP], KlS[64*ASP];
    __shared__ __nv_bfloat16 VhS[64*ASP], VlS[64*ASP];
    __shared__ float band[64*68];
    __shared__ int   msks[64];

    const int i0 = blockIdx.x * 64;
    const int h  = blockIdx.y;
    const int b  = blockIdx.z;
    const int bh = b*KH + h;
    const float* qb   = g_q + (size_t)bh*KS*KD;
    const float* kb   = g_k + (size_t)bh*KS*KD;
    const float* vb   = g_v + (size_t)bh*KS*KD;
    const float* c2pb = g_c2p + (size_t)bh*KS*KS;    // diagonalized [i][j]
    const float* p2cb = g_p2c + (size_t)bh*KS*KTP;

    const int tid = threadIdx.x;
    const int lane = tid & 31, warp = tid >> 5;
    const int wm = warp * 16;
    const int g = lane >> 2, tig = lane & 3;
    const int r0 = wm + g, r1 = r0 + 8;

    // ldmatrix lane bases
    const int rA = lane & 15, kA = (lane >> 4) * 8;           // A x4 (rows=m)
    const int rK4 = (lane & 7) + ((lane >> 4) & 1) * 8;       // K x4 paired nf
    const int kK4 = ((lane >> 3) & 1) * 8;
    const int rV4 = (lane & 7) + ((lane >> 3) & 1) * 8;       // V x4t paired nf
    const int dV4 = ((lane >> 4) & 1) * 8;

    const uint32_t khB = (uint32_t)__cvta_generic_to_shared(KhS) + (rK4*ASP + kK4)*2;
    const uint32_t klB = (uint32_t)__cvta_generic_to_shared(KlS) + (rK4*ASP + kK4)*2;
    const uint32_t vhB = (uint32_t)__cvta_generic_to_shared(VhS) + (rV4*ASP + dV4)*2;
    const uint32_t vlB = (uint32_t)__cvta_generic_to_shared(VlS) + (rV4*ASP + dV4)*2;
    const uint32_t qhB = (uint32_t)__cvta_generic_to_shared(KhS) + ((wm + rA)*ASP + kA)*2;
    const uint32_t qlB = (uint32_t)__cvta_generic_to_shared(KlS) + ((wm + rA)*ASP + kA)*2;

    // ---- stage Q through K buffers, load Q fragments once ----
    {
        const int row = tid >> 1, kb4 = (tid & 1) * 32;
        const float* src = qb + (size_t)(i0 + row)*KD + kb4;
        #pragma unroll
        for (int qq = 0; qq < 8; qq++)
            split4(*(const float4*)(src + qq*4), KhS, KlS, row*ASP + kb4 + qq*4);
    }
    __syncthreads();
    uint32_t qh[4][4], ql[4][4];
    #pragma unroll
    for (int t = 0; t < 4; t++) {
        ldsm_x4(qh[t][0], qh[t][1], qh[t][2], qh[t][3], qhB + t*32);
        ldsm_x4(ql[t][0], ql[t][1], ql[t][2], ql[t][3], qlB + t*32);
    }

    float m0 = -1e30f, m1 = -1e30f, l0 = 0.f, l1 = 0.f;
    float o[8][4] = {};

    for (int j0 = 0; j0 < KS; j0 += 64) {
        __syncthreads();

        // ---- stage K, V (split hi/lo) ----
        {
            const int row = tid >> 1, kb4 = (tid & 1) * 32;
            const float* ks = kb + (size_t)(j0 + row)*KD + kb4;
            const float* vs = vb + (size_t)(j0 + row)*KD + kb4;
            #pragma unroll
            for (int qq = 0; qq < 8; qq++) {
                split4(*(const float4*)(ks + qq*4), KhS, KlS, row*ASP + kb4 + qq*4);
                split4(*(const float4*)(vs + qq*4), VhS, VlS, row*ASP + kb4 + qq*4);
            }
        }
        // ---- stage p2c band: band[jl][x]; value for row r is band[jl][63-r] ----
        {
            const int c = tid >> 1, q2 = tid & 1;
            const float* src = p2cb + (size_t)(j0 + c)*KTP + (j0 + c - i0 + 320);
            #pragma unroll
            for (int xx = 0; xx < 32; xx++) {
                const int x = q2 + xx*2;
                band[c*68 + x] = src[x];
            }
        }
        if (tid < 64) msks[tid] = mask[b*KS + j0 + tid];
        __syncthreads();

        // ---- c2c: Q @ K^T  (K frags x4, 2 nf per ldsm) ----
        float sacc[8][4] = {};
        #pragma unroll
        for (int t = 0; t < 4; t++) {
            #pragma unroll
            for (int p = 0; p < 4; p++) {
                const uint32_t boff = (uint32_t)(p*16*ASP + t*16)*2;
                uint32_t b0h,b1h,b2h,b3h, b0l,b1l,b2l,b3l;
                ldsm_x4(b0h,b1h,b2h,b3h, khB + boff);
                ldsm_x4(b0l,b1l,b2l,b3l, klB + boff);
                mma_bf16(sacc[2*p],   qh[t][0],qh[t][1],qh[t][2],qh[t][3], b0h,b1h);
                mma_bf16(sacc[2*p],   qh[t][0],qh[t][1],qh[t][2],qh[t][3], b0l,b1l);
                mma_bf16(sacc[2*p],   ql[t][0],ql[t][1],ql[t][2],ql[t][3], b0h,b1h);
                mma_bf16(sacc[2*p+1], qh[t][0],qh[t][1],qh[t][2],qh[t][3], b2h,b3h);
                mma_bf16(sacc[2*p+1], qh[t][0],qh[t][1],qh[t][2],qh[t][3], b2l,b3l);
                mma_bf16(sacc[2*p+1], ql[t][0],ql[t][1],ql[t][2],ql[t][3], b2h,b3h);
            }
        }

        // ---- logits = (c2c + c2p + p2c)*SCALE, mask; in-warp row max ----
        const float* cr0 = c2pb + (size_t)(i0 + r0)*KS + j0;   // aligned, coalesced
        const float* cr1 = c2pb + (size_t)(i0 + r1)*KS + j0;
        float nm0 = m0, nm1 = m1;
        #pragma unroll
        for (int nf = 0; nf < 8; nf++) {
            const int jl = nf*8 + 2*tig;
            const float2 c0 = *(const float2*)(cr0 + jl);
            const float2 c1 = *(const float2*)(cr1 + jl);
            float v0 = (sacc[nf][0] + c0.x + band[jl*68     + 63 - r0]) * KSCALE;
            float v1 = (sacc[nf][1] + c0.y + band[(jl+1)*68 + 63 - r0]) * KSCALE;
            float v2 = (sacc[nf][2] + c1.x + band[jl*68     + 63 - r1]) * KSCALE;
            float v3 = (sacc[nf][3] + c1.y + band[(jl+1)*68 + 63 - r1]) * KSCALE;
            if (msks[jl]   == 0) { v0 = -9e15f; v2 = -9e15f; }
            if (msks[jl+1] == 0) { v1 = -9e15f; v3 = -9e15f; }
            sacc[nf][0] = v0; sacc[nf][1] = v1; sacc[nf][2] = v2; sacc[nf][3] = v3;
            nm0 = fmaxf(nm0, fmaxf(v0, v1));
            nm1 = fmaxf(nm1, fmaxf(v2, v3));
        }
        nm0 = fmaxf(nm0, __shfl_xor_sync(0xffffffffu, nm0, 1));
        nm0 = fmaxf(nm0, __shfl_xor_sync(0xffffffffu, nm0, 2));
        nm1 = fmaxf(nm1, __shfl_xor_sync(0xffffffffu, nm1, 1));
        nm1 = fmaxf(nm1, __shfl_xor_sync(0xffffffffu, nm1, 2));
        const float alpha0 = __expf(m0 - nm0);
        const float alpha1 = __expf(m1 - nm1);
        m0 = nm0; m1 = nm1;

        // ---- p = exp(l - m); in-warp row sums ----
        float s0 = 0.f, s1 = 0.f;
        #pragma unroll
        for (int nf = 0; nf < 8; nf++) {
            float p0 = __expf(sacc[nf][0] - m0);
            float p1 = __expf(sacc[nf][1] - m0);
            float p2 = __expf(sacc[nf][2] - m1);
            float p3 = __expf(sacc[nf][3] - m1);
            sacc[nf][0] = p0; sacc[nf][1] = p1; sacc[nf][2] = p2; sacc[nf][3] = p3;
            s0 += p0 + p1;  s1 += p2 + p3;
        }
        s0 += __shfl_xor_sync(0xffffffffu, s0, 1);
        s0 += __shfl_xor_sync(0xffffffffu, s0, 2);
        s1 += __shfl_xor_sync(0xffffffffu, s1, 1);
        s1 += __shfl_xor_sync(0xffffffffu, s1, 2);
        l0 = l0*alpha0 + s0;
        l1 = l1*alpha1 + s1;

        // ---- O rescale ----
        #pragma unroll
        for (int nf = 0; nf < 8; nf++) {
            o[nf][0] *= alpha0; o[nf][1] *= alpha0;
            o[nf][2] *= alpha1; o[nf][3] *= alpha1;
        }

        // ---- P @ V: pack A-frags in regs; V x4.trans, 2 nf per ldsm ----
        #pragma unroll
        for (int t = 0; t < 4; t++) {
            uint32_t pah[4], pal[4];
            {
                __nv_bfloat16 ha,la, hb,lb;
                bsplit(sacc[2*t][0], ha, la);  bsplit(sacc[2*t][1], hb, lb);
                pah[0] = pack2(ha,hb);  pal[0] = pack2(la,lb);
                bsplit(sacc[2*t][2], ha, la);  bsplit(sacc[2*t][3], hb, lb);
                pah[1] = pack2(ha,hb);  pal[1] = pack2(la,lb);
                bsplit(sacc[2*t+1][0], ha, la); bsplit(sacc[2*t+1][1], hb, lb);
                pah[2] = pack2(ha,hb);  pal[2] = pack2(la,lb);
                bsplit(sacc[2*t+1][2], ha, la); bsplit(sacc[2*t+1][3], hb, lb);
                pah[3] = pack2(ha,hb);  pal[3] = pack2(la,lb);
            }
            #pragma unroll
            for (int p = 0; p < 4; p++) {
                const uint32_t voff = (uint32_t)(t*16*ASP + p*16)*2;
                uint32_t vh0,vh1,vh2,vh3, vl0,vl1,vl2,vl3;
                ldsm_x4t(vh0,vh1,vh2,vh3, vhB + voff);
                ldsm_x4t(vl0,vl1,vl2,vl3, vlB + voff);
                mma_bf16(o[2*p],   pah[0],pah[1],pah[2],pah[3], vh0,vh1);
                mma_bf16(o[2*p],   pah[0],pah[1],pah[2],pah[3], vl0,vl1);
                mma_bf16(o[2*p],   pal[0],pal[1],pal[2],pal[3], vh0,vh1);
                mma_bf16(o[2*p+1], pah[0],pah[1],pah[2],pah[3], vh2,vh3);
                mma_bf16(o[2*p+1], pah[0],pah[1],pah[2],pah[3], vl2,vl3);
                mma_bf16(o[2*p+1], pal[0],pal[1],pal[2],pal[3], vh2,vh3);
            }
        }
    }

    // ---- normalize, store ctx [b][s][h*64+d] ----
    const float inv0 = 1.f / l0;
    const float inv1 = 1.f / l1;
    #pragma unroll
    for (int nf = 0; nf < 8; nf++) {
        const int d = nf*8 + 2*tig;
        float2 v0 = make_float2(o[nf][0]*inv0, o[nf][1]*inv0);
        float2 v1 = make_float2(o[nf][2]*inv1, o[nf][3]*inv1);
        *(float2*)(g_ctx + ((size_t)b*KS + i0 + r0)*KE + h*KD + d) = v0;
        *(float2*)(g_ctx + ((size_t)b*KS + i0 + r1)*KE + h*KD + d) = v1;
    }
}

// ---------------------------------------------------------------------------
// K6: output projection: out = ctx @ Wo^T + bo
// ---------------------------------------------------------------------------
__global__ void __launch_bounds__(256, 2)
out_kernel(const float* __restrict__ Wo, const float* __restrict__ bo,
           float* __restrict__ out)
{
    GEMM_SMEM
    const int m0 = blockIdx.y * 128;
    const int n0 = blockIdx.x * 128;

    float acc[4][4][4] = {};
    mma128_core(g_ctx, KE, m0, KB*KS, Wo, KE, n0, KIN, KE, acc, Ah, Al, Bh, Bl);

    const int lane = threadIdx.x & 31, warp = threadIdx.x >> 5;
    const int wm = (warp >> 2) * 64, wn = (warp & 3) * 32;
    const int g = lane >> 2, tig = lane & 3;
    #pragma unroll
    for (int mf = 0; mf < 4; mf++)
        #pragma unroll
        for (int nf = 0; nf < 4; nf++) {
            const int n = n0 + wn + nf*8 + 2*tig;
            const float2 bv2 = make_float2(bo[n], bo[n+1]);
            #pragma unroll
            for (int half = 0; half < 2; half++) {
                const int m = m0 + wm + mf*16 + g + half*8;
                float2 v;
                v.x = acc[mf][nf][half*2+0] + bv2.x;
                v.y = acc[mf][nf][half*2+1] + bv2.y;
                *(float2*)(out + (size_t)m*KIN + n) = v;
            }
        }
}

// ---------------------------------------------------------------------------
extern "C" void kernel_launch(void* const* d_in, const int* in_sizes, int n_in,
                              void* d_out, int out_size)
{
    const float* x    = (const float*)d_in[0];
    const int*   mask = (const int*)  d_in[1];
    const float* Wq   = (const float*)d_in[2];
    const float* bq   = (const float*)d_in[3];
    const float* Wk   = (const float*)d_in[4];
    const float* bk   = (const float*)d_in[5];
    const float* Wv   = (const float*)d_in[6];
    const float* bv   = (const float*)d_in[7];
    const float* rel  = (const float*)d_in[8];
    const float* Wpk  = (const float*)d_in[9];
    const float* bpk  = (const float*)d_in[10];
    const float* Wpq  = (const float*)d_in[11];
    const float* bpq  = (const float*)d_in[12];
    const float* Wo   = (const float*)d_in[13];
    const float* bo   = (const float*)d_in[14];

    dim3 thr(256);
    qkv_kernel   <<<dim3(1536/128, (KB*KS)/128), thr>>>(x, Wq, bq, Wk, bk, Wv, bv);
    pos_kernel   <<<dim3(1024/128, (KT + 127)/128), thr>>>(rel, Wpk, bpk, Wpq, bpq);
    disent_kernel<<<dim3((KT + 127)/128, KS/128, 2*KB*KH), thr>>>();
    attn_kernel  <<<dim3(KS/64, KH, KB), dim3(128)>>>(mask);
    out_kernel   <<<dim3(KIN/128, (KB*KS)/128), thr>>>(Wo, bo, (float*)d_out);
}

// round 16
// speedup vs baseline: 1.3329x; 1.0281x over previous
#include <cuda_runtime.h>
#include <cuda_bf16.h>
#include <cstdint>

// ---------------------------------------------------------------------------
// DeBERTa-style disentangled attention.
// B=8 S=384 IN=512 E=512 H=8 D=64, rel offsets t in [0,767), table row t+128.
// R16: q/k/v/pk/pq persisted in GLOBAL bf16 hi/lo form (split once at the
//      producer). disent uses a bf16-input GEMM core (copy loader, no cvt);
//      attn stages Q/K/V as raw uint4 copies. Same decomposition -> identical
//      numerics. c2p diagonalized (R15), p2c banded, MMA patterns unchanged.
// ---------------------------------------------------------------------------

#define KB 8
#define KS 384
#define KIN 512
#define KE 512
#define KH 8
#define KD 64
#define KT 767            // 2*S-1 (logical)
#define KTP 768           // padded row stride for p2c scratch
#define KRELOFF 128       // table row = t + 128
#define KSCALE 0.07216878364870323f   // 1/sqrt(64*3)

#define BKP 40            // bf16 smem row stride (elems) = 80B -> conflict-free
#define TSZ (128*BKP)     // one tile buffer (elems)
#define ASP 72            // attn bf16 smem row stride (elems) = 144B -> conflict-free

#define NQKV (KB*KH*KS*KD)
#define NPOS (KH*KT*KD)

__device__ __nv_bfloat16 g_qh[NQKV], g_ql[NQKV];
__device__ __nv_bfloat16 g_kh[NQKV], g_kl[NQKV];
__device__ __nv_bfloat16 g_vh[NQKV], g_vl[NQKV];
__device__ __nv_bfloat16 g_pkh[NPOS], g_pkl[NPOS];
__device__ __nv_bfloat16 g_pqh[NPOS], g_pql[NPOS];
__device__ float g_c2p[(size_t)KB*KH*KS*KS];   // diagonalized [bh][i][j]
__device__ float g_p2c[(size_t)KB*KH*KS*KTP];  // [bh][j][t]
__device__ float g_ctx[KB*KS*KE];

// ---------------------------------------------------------------------------
// bf16 / mma helpers
// ---------------------------------------------------------------------------
__device__ __forceinline__ void bsplit(float x, __nv_bfloat16& h, __nv_bfloat16& l)
{
    h = __float2bfloat16_rn(x);
    l = __float2bfloat16_rn(x - __bfloat162float(h));
}

__device__ __forceinline__ uint32_t pack2(__nv_bfloat16 a, __nv_bfloat16 b)
{
    __nv_bfloat162 t(a, b);
    return *reinterpret_cast<uint32_t*>(&t);
}

__device__ __forceinline__ void mma_bf16(float* d,
    uint32_t a0, uint32_t a1, uint32_t a2, uint32_t a3,
    uint32_t b0, uint32_t b1)
{
    asm("mma.sync.aligned.m16n8k16.row.col.f32.bf16.bf16.f32 "
        "{%0,%1,%2,%3}, {%4,%5,%6,%7}, {%8,%9}, {%0,%1,%2,%3};"
        : "+f"(d[0]), "+f"(d[1]), "+f"(d[2]), "+f"(d[3])
        : "r"(a0), "r"(a1), "r"(a2), "r"(a3), "r"(b0), "r"(b1));
}

__device__ __forceinline__ void ldsm_x4(uint32_t& r0, uint32_t& r1,
                                        uint32_t& r2, uint32_t& r3, uint32_t addr)
{
    asm volatile("ldmatrix.sync.aligned.m8n8.x4.shared.b16 {%0,%1,%2,%3}, [%4];"
        : "=r"(r0), "=r"(r1), "=r"(r2), "=r"(r3) : "r"(addr));
}

__device__ __forceinline__ void ldsm_x4t(uint32_t& r0, uint32_t& r1,
                                         uint32_t& r2, uint32_t& r3, uint32_t addr)
{
    asm volatile("ldmatrix.sync.aligned.m8n8.x4.trans.shared.b16 {%0,%1,%2,%3}, [%4];"
        : "=r"(r0), "=r"(r1), "=r"(r2), "=r"(r3) : "r"(addr));
}

__device__ __forceinline__ void split4(float4 v, __nv_bfloat16* H, __nv_bfloat16* L, int off)
{
    __nv_bfloat16 hx,hy,hz,hw, lx,ly,lz,lw;
    bsplit(v.x,hx,lx); bsplit(v.y,hy,ly);
    bsplit(v.z,hz,lz); bsplit(v.w,hw,lw);
    *(uint2*)&H[off] = make_uint2(pack2(hx,hy), pack2(hz,hw));
    *(uint2*)&L[off] = make_uint2(pack2(lx,ly), pack2(lz,lw));
}

// ---------------------------------------------------------------------------
// 128x128 tile GEMM core, f32 inputs (splits in loader). 256 thr, BK=32.
// ---------------------------------------------------------------------------
__device__ __forceinline__ void mma128_core(
    const float* __restrict__ A, int lda, int a0r, int Mlim,
    const float* __restrict__ Bm, int ldb, int b0r, int Nlim,
    int K, float acc[4][4][4],
    __nv_bfloat16* Ah, __nv_bfloat16* Al,
    __nv_bfloat16* Bh, __nv_bfloat16* Bl)
{
    const int tid = threadIdx.x;
    const int lane = tid & 31, warp = tid >> 5;
    const int wm = (warp >> 2) * 64;
    const int wn = (warp & 3) * 32;
    const int lrow = tid >> 3;
    const int lk = (tid & 7) * 4;

    const int rA = lane & 15, kA = (lane >> 4) * 8;
    const int rB4 = (lane & 7) + ((lane >> 4) & 1) * 8;
    const int kB4 = ((lane >> 3) & 1) * 8;
    const uint32_t aHb = (uint32_t)__cvta_generic_to_shared(Ah) + ((wm + rA)*BKP + kA)*2;
    const uint32_t aLb = (uint32_t)__cvta_generic_to_shared(Al) + ((wm + rA)*BKP + kA)*2;
    const uint32_t bHb = (uint32_t)__cvta_generic_to_shared(Bh) + ((wn + rB4)*BKP + kB4)*2;
    const uint32_t bLb = (uint32_t)__cvta_generic_to_shared(Bl) + ((wn + rB4)*BKP + kB4)*2;

    for (int k0 = 0; k0 < K; k0 += 32) {
        __syncthreads();
        #pragma unroll
        for (int h4 = 0; h4 < 4; h4++) {
            const int row = lrow + h4 * 32;
            {
                const int ar = a0r + row;
                float4 v = make_float4(0.f, 0.f, 0.f, 0.f);
                if (ar < Mlim)
                    v = *(const float4*)(A + (size_t)ar * lda + k0 + lk);
                split4(v, Ah, Al, row*BKP + lk);
            }
            {
                const int br = b0r + row;
                float4 v = make_float4(0.f, 0.f, 0.f, 0.f);
                if (br < Nlim)
                    v = *(const float4*)(Bm + (size_t)br * ldb + k0 + lk);
                split4(v, Bh, Bl, row*BKP + lk);
            }
        }
        __syncthreads();
        #pragma unroll
        for (int kk = 0; kk < 32; kk += 16) {
            uint32_t bh_[4][2], bl_[4][2];
            #pragma unroll
            for (int p = 0; p < 2; p++) {
                const uint32_t boff = (uint32_t)(p*16*BKP + kk) * 2;
                ldsm_x4(bh_[2*p][0], bh_[2*p][1], bh_[2*p+1][0], bh_[2*p+1][1], bHb + boff);
                ldsm_x4(bl_[2*p][0], bl_[2*p][1], bl_[2*p+1][0], bl_[2*p+1][1], bLb + boff);
            }
            #pragma unroll
            for (int mf = 0; mf < 4; mf++) {
                const uint32_t aoff = (uint32_t)(mf*16*BKP + kk) * 2;
                uint32_t ah0,ah1,ah2,ah3, al0,al1,al2,al3;
                ldsm_x4(ah0,ah1,ah2,ah3, aHb + aoff);
                ldsm_x4(al0,al1,al2,al3, aLb + aoff);
                #pragma unroll
                for (int nf = 0; nf < 4; nf++) {
                    mma_bf16(acc[mf][nf], ah0,ah1,ah2,ah3, bh_[nf][0], bh_[nf][1]);
                    mma_bf16(acc[mf][nf], ah0,ah1,ah2,ah3, bl_[nf][0], bl_[nf][1]);
                    mma_bf16(acc[mf][nf], al0,al1,al2,al3, bh_[nf][0], bh_[nf][1]);
                }
            }
        }
    }
}

// ---------------------------------------------------------------------------
// Same core, bf16 hi/lo global inputs (pure copy loader, no conversion).
// ---------------------------------------------------------------------------
__device__ __forceinline__ void mma128_core_bf(
    const __nv_bfloat16* __restrict__ Agh, const __nv_bfloat16* __restrict__ Agl,
    int lda, int a0r, int Mlim,
    const __nv_bfloat16* __restrict__ Bgh, const __nv_bfloat16* __restrict__ Bgl,
    int ldb, int b0r, int Nlim,
    int K, float acc[4][4][4],
    __nv_bfloat16* Ah, __nv_bfloat16* Al,
    __nv_bfloat16* Bh, __nv_bfloat16* Bl)
{
    const int tid = threadIdx.x;
    const int lane = tid & 31, warp = tid >> 5;
    const int wm = (warp >> 2) * 64;
    const int wn = (warp & 3) * 32;
    const int lrow = tid >> 3;
    const int lk = (tid & 7) * 4;

    const int rA = lane & 15, kA = (lane >> 4) * 8;
    const int rB4 = (lane & 7) + ((lane >> 4) & 1) * 8;
    const int kB4 = ((lane >> 3) & 1) * 8;
    const uint32_t aHb = (uint32_t)__cvta_generic_to_shared(Ah) + ((wm + rA)*BKP + kA)*2;
    const uint32_t aLb = (uint32_t)__cvta_generic_to_shared(Al) + ((wm + rA)*BKP + kA)*2;
    const uint32_t bHb = (uint32_t)__cvta_generic_to_shared(Bh) + ((wn + rB4)*BKP + kB4)*2;
    const uint32_t bLb = (uint32_t)__cvta_generic_to_shared(Bl) + ((wn + rB4)*BKP + kB4)*2;

    const uint2 z2 = make_uint2(0u, 0u);
    for (int k0 = 0; k0 < K; k0 += 32) {
        __syncthreads();
        #pragma unroll
        for (int h4 = 0; h4 < 4; h4++) {
            const int row = lrow + h4 * 32;
            {
                const int ar = a0r + row;
                uint2 vh = z2, vl = z2;
                if (ar < Mlim) {
                    const size_t off = (size_t)ar * lda + k0 + lk;
                    vh = *(const uint2*)(Agh + off);
                    vl = *(const uint2*)(Agl + off);
                }
                *(uint2*)&Ah[row*BKP + lk] = vh;
                *(uint2*)&Al[row*BKP + lk] = vl;
            }
            {
                const int br = b0r + row;
                uint2 vh = z2, vl = z2;
                if (br < Nlim) {
                    const size_t off = (size_t)br * ldb + k0 + lk;
                    vh = *(const uint2*)(Bgh + off);
                    vl = *(const uint2*)(Bgl + off);
                }
                *(uint2*)&Bh[row*BKP + lk] = vh;
                *(uint2*)&Bl[row*BKP + lk] = vl;
            }
        }
        __syncthreads();
        #pragma unroll
        for (int kk = 0; kk < 32; kk += 16) {
            uint32_t bh_[4][2], bl_[4][2];
            #pragma unroll
            for (int p = 0; p < 2; p++) {
                const uint32_t boff = (uint32_t)(p*16*BKP + kk) * 2;
                ldsm_x4(bh_[2*p][0], bh_[2*p][1], bh_[2*p+1][0], bh_[2*p+1][1], bHb + boff);
                ldsm_x4(bl_[2*p][0], bl_[2*p][1], bl_[2*p+1][0], bl_[2*p+1][1], bLb + boff);
            }
            #pragma unroll
            for (int mf = 0; mf < 4; mf++) {
                const uint32_t aoff = (uint32_t)(mf*16*BKP + kk) * 2;
                uint32_t ah0,ah1,ah2,ah3, al0,al1,al2,al3;
                ldsm_x4(ah0,ah1,ah2,ah3, aHb + aoff);
                ldsm_x4(al0,al1,al2,al3, aLb + aoff);
                #pragma unroll
                for (int nf = 0; nf < 4; nf++) {
                    mma_bf16(acc[mf][nf], ah0,ah1,ah2,ah3, bh_[nf][0], bh_[nf][1]);
                    mma_bf16(acc[mf][nf], ah0,ah1,ah2,ah3, bl_[nf][0], bl_[nf][1]);
                    mma_bf16(acc[mf][nf], al0,al1,al2,al3, bh_[nf][0], bh_[nf][1]);
                }
            }
        }
    }
}

#define GEMM_SMEM \
    __shared__ __nv_bfloat16 Ah[TSZ], Al[TSZ], Bh[TSZ], Bl[TSZ];

// ---------------------------------------------------------------------------
// K1: fused QKV projection -> bf16 hi/lo outputs.
// ---------------------------------------------------------------------------
__global__ void __launch_bounds__(256, 2)
qkv_kernel(const float* __restrict__ x,
           const float* __restrict__ Wq, const float* __restrict__ bq,
           const float* __restrict__ Wk, const float* __restrict__ bk,
           const float* __restrict__ Wv, const float* __restrict__ bv)
{
    GEMM_SMEM
    const int m0 = blockIdx.y * 128;
    const int n0 = blockIdx.x * 128;
    const int which = n0 >> 9;
    const float* W    = (which == 0) ? Wq : (which == 1) ? Wk : Wv;
    const float* bias = (which == 0) ? bq : (which == 1) ? bk : bv;
    __nv_bfloat16* dsth = (which == 0) ? g_qh : (which == 1) ? g_kh : g_vh;
    __nv_bfloat16* dstl = (which == 0) ? g_ql : (which == 1) ? g_kl : g_vl;
    const int e0 = n0 & 511;

    float acc[4][4][4] = {};
    mma128_core(x, KIN, m0, KB*KS, W, KIN, e0, KE, KIN, acc, Ah, Al, Bh, Bl);

    const int lane = threadIdx.x & 31, warp = threadIdx.x >> 5;
    const int wm = (warp >> 2) * 64, wn = (warp & 3) * 32;
    const int g = lane >> 2, tig = lane & 3;
    #pragma unroll
    for (int mf = 0; mf < 4; mf++)
        #pragma unroll
        for (int nf = 0; nf < 4; nf++) {
            const int e = e0 + wn + nf*8 + 2*tig;       // even
            const int h = e >> 6, d0 = e & 63;
            const float2 bv2 = make_float2(bias[e], bias[e+1]);
            #pragma unroll
            for (int half = 0; half < 2; half++) {
                const int m = m0 + wm + mf*16 + g + half*8;
                const int b = m / KS, s = m % KS;
                const float vx = acc[mf][nf][half*2+0] + bv2.x;
                const float vy = acc[mf][nf][half*2+1] + bv2.y;
                __nv_bfloat16 h0,l0, h1,l1;
                bsplit(vx,h0,l0); bsplit(vy,h1,l1);
                const size_t off = ((size_t)(b*KH + h)*KS + s)*KD + d0;
                *(uint32_t*)&dsth[off] = pack2(h0,h1);
                *(uint32_t*)&dstl[off] = pack2(l0,l1);
            }
        }
}

// ---------------------------------------------------------------------------
// K2: positional projections PK[t] / PQ[t] -> bf16 hi/lo outputs.
// ---------------------------------------------------------------------------
__global__ void __launch_bounds__(256, 2)
pos_kernel(const float* __restrict__ rel_table,
           const float* __restrict__ Wpk, const float* __restrict__ bpk,
           const float* __restrict__ Wpq, const float* __restrict__ bpq)
{
    GEMM_SMEM
    const int m0 = blockIdx.y * 128;
    const int n0 = blockIdx.x * 128;
    const bool isq = (n0 >= 512);
    const float* W    = isq ? Wpq : Wpk;
    const float* bias = isq ? bpq : bpk;
    __nv_bfloat16* dsth = isq ? g_pqh : g_pkh;
    __nv_bfloat16* dstl = isq ? g_pql : g_pkl;
    const int e0 = n0 & 511;

    float acc[4][4][4] = {};
    mma128_core(rel_table + (size_t)KRELOFF*KIN, KIN, m0, KT,
                W, KIN, e0, KE, KIN, acc, Ah, Al, Bh, Bl);

    const int lane = threadIdx.x & 31, warp = threadIdx.x >> 5;
    const int wm = (warp >> 2) * 64, wn = (warp & 3) * 32;
    const int g = lane >> 2, tig = lane & 3;
    #pragma unroll
    for (int mf = 0; mf < 4; mf++)
        #pragma unroll
        for (int nf = 0; nf < 4; nf++) {
            const int e = e0 + wn + nf*8 + 2*tig;
            const int h = e >> 6, d0 = e & 63;
            const float2 bv2 = make_float2(bias[e], bias[e+1]);
            #pragma unroll
            for (int half = 0; half < 2; half++) {
                const int t = m0 + wm + mf*16 + g + half*8;
                if (t >= KT) continue;
                const float vx = acc[mf][nf][half*2+0] + bv2.x;
                const float vy = acc[mf][nf][half*2+1] + bv2.y;
                __nv_bfloat16 h0,l0, h1,l1;
                bsplit(vx,h0,l0); bsplit(vy,h1,l1);
                const size_t off = ((size_t)h*KT + t)*KD + d0;
                *(uint32_t*)&dsth[off] = pack2(h0,h1);
                *(uint32_t*)&dstl[off] = pack2(l0,l1);
            }
        }
}

// ---------------------------------------------------------------------------
// K3: disentangled score tables (bf16-input core), both passes per launch.
//   which==0: C2P diagonalized store c2pd[bh][i][j], j=t+i-383
//   which==1: P2C[bh][j][t] stride KTP
// ---------------------------------------------------------------------------
__global__ void __launch_bounds__(256, 2)
disent_kernel()
{
    const int which = blockIdx.z >> 6;
    const int bh = blockIdx.z & 63;
    const int i0 = blockIdx.y * 128;
    const int t0 = blockIdx.x * 128;
    const int r_max = (i0 + 127 < KS - 1) ? i0 + 127 : KS - 1;
    int t_lo, t_hi;
    if (which == 0) { t_lo = (KS - 1) - r_max;  t_hi = (2*KS - 2) - i0; }
    else            { t_lo = i0;                t_hi = r_max + (KS - 1); }
    if (t0 > t_hi || t0 + 127 < t_lo) return;

    GEMM_SMEM
    const int h  = bh & 7;
    const __nv_bfloat16* vh_ = which ? g_kh : g_qh;
    const __nv_bfloat16* vl_ = which ? g_kl : g_ql;
    const __nv_bfloat16* ph_ = which ? g_pqh : g_pkh;
    const __nv_bfloat16* pl_ = which ? g_pql : g_pkl;

    float acc[4][4][4] = {};
    mma128_core_bf(vh_ + (size_t)bh*KS*KD, vl_ + (size_t)bh*KS*KD, KD, i0, KS,
                   ph_ + (size_t)h*KT*KD,  pl_ + (size_t)h*KT*KD,  KD, t0, KT,
                   KD, acc, Ah, Al, Bh, Bl);

    const int lane = threadIdx.x & 31, warp = threadIdx.x >> 5;
    const int wm = (warp >> 2) * 64, wn = (warp & 3) * 32;
    const int g = lane >> 2, tig = lane & 3;

    if (which == 0) {
        #pragma unroll
        for (int mf = 0; mf < 4; mf++)
            #pragma unroll
            for (int half = 0; half < 2; half++) {
                const int i = i0 + wm + mf*16 + g + half*8;
                float* orow = g_c2p + ((size_t)bh*KS + i)*KS;
                const int jb = i - (KS - 1);
                #pragma unroll
                for (int nf = 0; nf < 4; nf++) {
                    const int t = t0 + wn + nf*8 + 2*tig;
                    const int j = t + jb;
                    if ((unsigned)j < KS)     orow[j]   = acc[mf][nf][half*2+0];
                    if ((unsigned)(j+1) < KS) orow[j+1] = acc[mf][nf][half*2+1];
                }
            }
    } else {
        #pragma unroll
        for (int mf = 0; mf < 4; mf++)
            #pragma unroll
            for (int half = 0; half < 2; half++) {
                const int i = i0 + wm + mf*16 + g + half*8;
                float* orow = g_p2c + ((size_t)bh*KS + i)*KTP;
                #pragma unroll
                for (int nf = 0; nf < 4; nf++) {
                    const int t = t0 + wn + nf*8 + 2*tig;
                    float2 v;
                    v.x = acc[mf][nf][half*2+0];
                    v.y = acc[mf][nf][half*2+1];
                    *(float2*)(orow + t) = v;
                }
            }
    }
}

// ---------------------------------------------------------------------------
// K5: flash attention, register-resident; Q/K/V staged by raw uint4 copies
// from the global bf16 hi/lo arrays. 128 threads / 4 warps.
// ---------------------------------------------------------------------------
__global__ void __launch_bounds__(128, 3)
attn_kernel(const int* __restrict__ mask)
{
    __shared__ __nv_bfloat16 KhS[64*ASP], KlS[64*ASP];
    __shared__ __nv_bfloat16 VhS[64*ASP], VlS[64*ASP];
    __shared__ float band[64*68];
    __shared__ int   msks[64];

    const int i0 = blockIdx.x * 64;
    const int h  = blockIdx.y;
    const int b  = blockIdx.z;
    const int bh = b*KH + h;
    const __nv_bfloat16* qhb = g_qh + (size_t)bh*KS*KD;
    const __nv_bfloat16* qlb = g_ql + (size_t)bh*KS*KD;
    const __nv_bfloat16* khb = g_kh + (size_t)bh*KS*KD;
    const __nv_bfloat16* klb = g_kl + (size_t)bh*KS*KD;
    const __nv_bfloat16* vhb = g_vh + (size_t)bh*KS*KD;
    const __nv_bfloat16* vlb = g_vl + (size_t)bh*KS*KD;
    const float* c2pb = g_c2p + (size_t)bh*KS*KS;
    const float* p2cb = g_p2c + (size_t)bh*KS*KTP;

    const int tid = threadIdx.x;
    const int lane = tid & 31, warp = tid >> 5;
    const int wm = warp * 16;
    const int g = lane >> 2, tig = lane & 3;
    const int r0 = wm + g, r1 = r0 + 8;

    const int rA = lane & 15, kA = (lane >> 4) * 8;
    const int rK4 = (lane & 7) + ((lane >> 4) & 1) * 8;
    const int kK4 = ((lane >> 3) & 1) * 8;
    const int rV4 = (lane & 7) + ((lane >> 3) & 1) * 8;
    const int dV4 = ((lane >> 4) & 1) * 8;

    const uint32_t khB = (uint32_t)__cvta_generic_to_shared(KhS) + (rK4*ASP + kK4)*2;
    const uint32_t klB = (uint32_t)__cvta_generic_to_shared(KlS) + (rK4*ASP + kK4)*2;
    const uint32_t vhB = (uint32_t)__cvta_generic_to_shared(VhS) + (rV4*ASP + dV4)*2;
    const uint32_t vlB = (uint32_t)__cvta_generic_to_shared(VlS) + (rV4*ASP + dV4)*2;
    const uint32_t qhB = (uint32_t)__cvta_generic_to_shared(KhS) + ((wm + rA)*ASP + kA)*2;
    const uint32_t qlB = (uint32_t)__cvta_generic_to_shared(KlS) + ((wm + rA)*ASP + kA)*2;

    const int srow = tid >> 1, scol = (tid & 1) * 32;   // staging map

    // ---- stage Q through K buffers (raw copies), load Q fragments once ----
    {
        const size_t off = (size_t)(i0 + srow)*KD + scol;
        #pragma unroll
        for (int qq = 0; qq < 4; qq++) {
            *(uint4*)&KhS[srow*ASP + scol + qq*8] = *(const uint4*)(qhb + off + qq*8);
            *(uint4*)&KlS[srow*ASP + scol + qq*8] = *(const uint4*)(qlb + off + qq*8);
        }
    }
    __syncthreads();
    uint32_t qh[4][4], ql[4][4];
    #pragma unroll
    for (int t = 0; t < 4; t++) {
        ldsm_x4(qh[t][0], qh[t][1], qh[t][2], qh[t][3], qhB + t*32);
        ldsm_x4(ql[t][0], ql[t][1], ql[t][2], ql[t][3], qlB + t*32);
    }

    float m0 = -1e30f, m1 = -1e30f, l0 = 0.f, l1 = 0.f;
    float o[8][4] = {};

    for (int j0 = 0; j0 < KS; j0 += 64) {
        __syncthreads();

        // ---- stage K, V (raw hi/lo copies) ----
        {
            const size_t off = (size_t)(j0 + srow)*KD + scol;
            #pragma unroll
            for (int qq = 0; qq < 4; qq++) {
                *(uint4*)&KhS[srow*ASP + scol + qq*8] = *(const uint4*)(khb + off + qq*8);
                *(uint4*)&KlS[srow*ASP + scol + qq*8] = *(const uint4*)(klb + off + qq*8);
                *(uint4*)&VhS[srow*ASP + scol + qq*8] = *(const uint4*)(vhb + off + qq*8);
                *(uint4*)&VlS[srow*ASP + scol + qq*8] = *(const uint4*)(vlb + off + qq*8);
            }
        }
        // ---- stage p2c band: band[jl][x]; value for row r is band[jl][63-r] ----
        {
            const int c = tid >> 1, q2 = tid & 1;
            const float* src = p2cb + (size_t)(j0 + c)*KTP + (j0 + c - i0 + 320);
            #pragma unroll
            for (int xx = 0; xx < 32; xx++) {
                const int x = q2 + xx*2;
                band[c*68 + x] = src[x];
            }
        }
        if (tid < 64) msks[tid] = mask[b*KS + j0 + tid];
        __syncthreads();

        // ---- c2c: Q @ K^T ----
        float sacc[8][4] = {};
        #pragma unroll
        for (int t = 0; t < 4; t++) {
            #pragma unroll
            for (int p = 0; p < 4; p++) {
                const uint32_t boff = (uint32_t)(p*16*ASP + t*16)*2;
                uint32_t b0h,b1h,b2h,b3h, b0l,b1l,b2l,b3l;
                ldsm_x4(b0h,b1h,b2h,b3h, khB + boff);
                ldsm_x4(b0l,b1l,b2l,b3l, klB + boff);
                mma_bf16(sacc[2*p],   qh[t][0],qh[t][1],qh[t][2],qh[t][3], b0h,b1h);
                mma_bf16(sacc[2*p],   qh[t][0],qh[t][1],qh[t][2],qh[t][3], b0l,b1l);
                mma_bf16(sacc[2*p],   ql[t][0],ql[t][1],ql[t][2],ql[t][3], b0h,b1h);
                mma_bf16(sacc[2*p+1], qh[t][0],qh[t][1],qh[t][2],qh[t][3], b2h,b3h);
                mma_bf16(sacc[2*p+1], qh[t][0],qh[t][1],qh[t][2],qh[t][3], b2l,b3l);
                mma_bf16(sacc[2*p+1], ql[t][0],ql[t][1],ql[t][2],ql[t][3], b2h,b3h);
            }
        }

        // ---- logits, mask, in-warp row max ----
        const float* cr0 = c2pb + (size_t)(i0 + r0)*KS + j0;
        const float* cr1 = c2pb + (size_t)(i0 + r1)*KS + j0;
        float nm0 = m0, nm1 = m1;
        #pragma unroll
        for (int nf = 0; nf < 8; nf++) {
            const int jl = nf*8 + 2*tig;
            const float2 c0 = *(const float2*)(cr0 + jl);
            const float2 c1 = *(const float2*)(cr1 + jl);
            float v0 = (sacc[nf][0] + c0.x + band[jl*68     + 63 - r0]) * KSCALE;
            float v1 = (sacc[nf][1] + c0.y + band[(jl+1)*68 + 63 - r0]) * KSCALE;
            float v2 = (sacc[nf][2] + c1.x + band[jl*68     + 63 - r1]) * KSCALE;
            float v3 = (sacc[nf][3] + c1.y + band[(jl+1)*68 + 63 - r1]) * KSCALE;
            if (msks[jl]   == 0) { v0 = -9e15f; v2 = -9e15f; }
            if (msks[jl+1] == 0) { v1 = -9e15f; v3 = -9e15f; }
            sacc[nf][0] = v0; sacc[nf][1] = v1; sacc[nf][2] = v2; sacc[nf][3] = v3;
            nm0 = fmaxf(nm0, fmaxf(v0, v1));
            nm1 = fmaxf(nm1, fmaxf(v2, v3));
        }
        nm0 = fmaxf(nm0, __shfl_xor_sync(0xffffffffu, nm0, 1));
        nm0 = fmaxf(nm0, __shfl_xor_sync(0xffffffffu, nm0, 2));
        nm1 = fmaxf(nm1, __shfl_xor_sync(0xffffffffu, nm1, 1));
        nm1 = fmaxf(nm1, __shfl_xor_sync(0xffffffffu, nm1, 2));
        const float alpha0 = __expf(m0 - nm0);
        const float alpha1 = __expf(m1 - nm1);
        m0 = nm0; m1 = nm1;

        // ---- p = exp(l - m); in-warp row sums ----
        float s0 = 0.f, s1 = 0.f;
        #pragma unroll
        for (int nf = 0; nf < 8; nf++) {
            float p0 = __expf(sacc[nf][0] - m0);
            float p1 = __expf(sacc[nf][1] - m0);
            float p2 = __expf(sacc[nf][2] - m1);
            float p3 = __expf(sacc[nf][3] - m1);
            sacc[nf][0] = p0; sacc[nf][1] = p1; sacc[nf][2] = p2; sacc[nf][3] = p3;
            s0 += p0 + p1;  s1 += p2 + p3;
        }
        s0 += __shfl_xor_sync(0xffffffffu, s0, 1);
        s0 += __shfl_xor_sync(0xffffffffu, s0, 2);
        s1 += __shfl_xor_sync(0xffffffffu, s1, 1);
        s1 += __shfl_xor_sync(0xffffffffu, s1, 2);
        l0 = l0*alpha0 + s0;
        l1 = l1*alpha1 + s1;

        // ---- O rescale ----
        #pragma unroll
        for (int nf = 0; nf < 8; nf++) {
            o[nf][0] *= alpha0; o[nf][1] *= alpha0;
            o[nf][2] *= alpha1; o[nf][3] *= alpha1;
        }

        // ---- P @ V ----
        #pragma unroll
        for (int t = 0; t < 4; t++) {
            uint32_t pah[4], pal[4];
            {
                __nv_bfloat16 ha,la, hb,lb;
                bsplit(sacc[2*t][0], ha, la);  bsplit(sacc[2*t][1], hb, lb);
                pah[0] = pack2(ha,hb);  pal[0] = pack2(la,lb);
                bsplit(sacc[2*t][2], ha, la);  bsplit(sacc[2*t][3], hb, lb);
                pah[1] = pack2(ha,hb);  pal[1] = pack2(la,lb);
                bsplit(sacc[2*t+1][0], ha, la); bsplit(sacc[2*t+1][1], hb, lb);
                pah[2] = pack2(ha,hb);  pal[2] = pack2(la,lb);
                bsplit(sacc[2*t+1][2], ha, la); bsplit(sacc[2*t+1][3], hb, lb);
                pah[3] = pack2(ha,hb);  pal[3] = pack2(la,lb);
            }
            #pragma unroll
            for (int p = 0; p < 4; p++) {
                const uint32_t voff = (uint32_t)(t*16*ASP + p*16)*2;
                uint32_t vh0,vh1,vh2,vh3, vl0,vl1,vl2,vl3;
                ldsm_x4t(vh0,vh1,vh2,vh3, vhB + voff);
                ldsm_x4t(vl0,vl1,vl2,vl3, vlB + voff);
                mma_bf16(o[2*p],   pah[0],pah[1],pah[2],pah[3], vh0,vh1);
                mma_bf16(o[2*p],   pah[0],pah[1],pah[2],pah[3], vl0,vl1);
                mma_bf16(o[2*p],   pal[0],pal[1],pal[2],pal[3], vh0,vh1);
                mma_bf16(o[2*p+1], pah[0],pah[1],pah[2],pah[3], vh2,vh3);
                mma_bf16(o[2*p+1], pah[0],pah[1],pah[2],pah[3], vl2,vl3);
                mma_bf16(o[2*p+1], pal[0],pal[1],pal[2],pal[3], vh2,vh3);
            }
        }
    }

    // ---- normalize, store ctx ----
    const float inv0 = 1.f / l0;
    const float inv1 = 1.f / l1;
    #pragma unroll
    for (int nf = 0; nf < 8; nf++) {
        const int d = nf*8 + 2*tig;
        float2 v0 = make_float2(o[nf][0]*inv0, o[nf][1]*inv0);
        float2 v1 = make_float2(o[nf][2]*inv1, o[nf][3]*inv1);
        *(float2*)(g_ctx + ((size_t)b*KS + i0 + r0)*KE + h*KD + d) = v0;
        *(float2*)(g_ctx + ((size_t)b*KS + i0 + r1)*KE + h*KD + d) = v1;
    }
}

// ---------------------------------------------------------------------------
// K6: output projection: out = ctx @ Wo^T + bo  (f32 core)
// ---------------------------------------------------------------------------
__global__ void __launch_bounds__(256, 2)
out_kernel(const float* __restrict__ Wo, const float* __restrict__ bo,
           float* __restrict__ out)
{
    GEMM_SMEM
    const int m0 = blockIdx.y * 128;
    const int n0 = blockIdx.x * 128;

    float acc[4][4][4] = {};
    mma128_core(g_ctx, KE, m0, KB*KS, Wo, KE, n0, KIN, KE, acc, Ah, Al, Bh, Bl);

    const int lane = threadIdx.x & 31, warp = threadIdx.x >> 5;
    const int wm = (warp >> 2) * 64, wn = (warp & 3) * 32;
    const int g = lane >> 2, tig = lane & 3;
    #pragma unroll
    for (int mf = 0; mf < 4; mf++)
        #pragma unroll
        for (int nf = 0; nf < 4; nf++) {
            const int n = n0 + wn + nf*8 + 2*tig;
            const float2 bv2 = make_float2(bo[n], bo[n+1]);
            #pragma unroll
            for (int half = 0; half < 2; half++) {
                const int m = m0 + wm + mf*16 + g + half*8;
                float2 v;
                v.x = acc[mf][nf][half*2+0] + bv2.x;
                v.y = acc[mf][nf][half*2+1] + bv2.y;
                *(float2*)(out + (size_t)m*KIN + n) = v;
            }
        }
}

// ---------------------------------------------------------------------------
extern "C" void kernel_launch(void* const* d_in, const int* in_sizes, int n_in,
                              void* d_out, int out_size)
{
    const float* x    = (const float*)d_in[0];
    const int*   mask = (const int*)  d_in[1];
    const float* Wq   = (const float*)d_in[2];
    const float* bq   = (const float*)d_in[3];
    const float* Wk   = (const float*)d_in[4];
    const float* bk   = (const float*)d_in[5];
    const float* Wv   = (const float*)d_in[6];
    const float* bv   = (const float*)d_in[7];
    const float* rel  = (const float*)d_in[8];
    const float* Wpk  = (const float*)d_in[9];
    const float* bpk  = (const float*)d_in[10];
    const float* Wpq  = (const float*)d_in[11];
    const float* bpq  = (const float*)d_in[12];
    const float* Wo   = (const float*)d_in[13];
    const float* bo   = (const float*)d_in[14];

    dim3 thr(256);
    qkv_kernel   <<<dim3(1536/128, (KB*KS)/128), thr>>>(x, Wq, bq, Wk, bk, Wv, bv);
    pos_kernel   <<<dim3(1024/128, (KT + 127)/128), thr>>>(rel, Wpk, bpk, Wpq, bpq);
    disent_kernel<<<dim3((KT + 127)/128, KS/128, 2*KB*KH), thr>>>();
    attn_kernel  <<<dim3(KS/64, KH, KB), dim3(128)>>>(mask);
    out_kernel   <<<dim3(KIN/128, (KB*KS)/128), thr>>>(Wo, bo, (float*)d_out);
}